// round 1
// baseline (speedup 1.0000x reference)
#include <cuda_runtime.h>
#include <math.h>

// Problem constants
#define B_  2
#define T_  64
#define N_  64
#define BT  128                      // B*T
#define NEDGE (BT * N_ * N_)         // 524288
#define V_SZ  ((size_t)BT * N_ * 256)       // 2097152
#define E_SZ  ((size_t)NEDGE * 128)         // 67108864
#define OFF_E  (V_SZ)
#define OFF_EI (OFF_E + E_SZ)               // 69206016
#define OFF_AB (OFF_EI + (size_t)NEDGE)     // 69730304

// Scratch (allowed: __device__ globals)
__device__ int   g_nbr[NEDGE];
__device__ int   g_abs[NEDGE];
__device__ float g_dnb[NEDGE];
__device__ float g_postab[575 * 16];

// ---------------------------------------------------------------------------
// Positional-encoding table: d in [-63, 511] -> 16 values [cos(d*f0..f7), sin(...)]
// Built with accurate cosf/sinf (args up to ~511 rad: __cosf would be too lossy).
// ---------------------------------------------------------------------------
__global__ void init_postab_kernel() {
    int idx = blockIdx.x * blockDim.x + threadIdx.x;
    if (idx >= 575 * 16) return;
    int dpos = idx >> 4;
    int k = idx & 15;
    float d = (float)(dpos - 63);
    int j = k & 7;
    float fr = expf((float)(2 * j) * (float)(-0.5756462732485114)); // -ln(1e4)/16
    float ang = d * fr;
    g_postab[idx] = (k < 8) ? cosf(ang) : sinf(ang);
}

// ---------------------------------------------------------------------------
// Kernel A: per (b,t) distance matrix + exact stable argsort (rank counting).
// Writes E_idx / abs_E_idx (float) straight into d_out + int/float scratch.
// ---------------------------------------------------------------------------
__global__ __launch_bounds__(256) void sort_kernel(
    const float* __restrict__ X, const float* __restrict__ mask,
    const int* __restrict__ focus, float* __restrict__ out)
{
    int bt = blockIdx.x;
    int tid = threadIdx.x;
    __shared__ float xca[64][3];
    __shared__ float msk[64];
    __shared__ float D[64][65];
    __shared__ float dmax[64];
    __shared__ int   eidx[64][64];
    __shared__ int   foc[64];

    for (int idx = tid; idx < 192; idx += 256) {
        int i = idx / 3, c = idx - i * 3;
        xca[i][c] = X[(size_t)(bt * 64 + i) * 12 + 3 + c];   // atom 1 = CA
    }
    for (int i = tid; i < 64; i += 256) {
        msk[i] = mask[bt * 64 + i];
        foc[i] = focus[bt * 64 + i];
    }
    __syncthreads();

    // D = mask2d * sqrt(|dX|^2 + 1e-6)  (non-contracted to match XLA rounding)
    for (int idx = tid; idx < 4096; idx += 256) {
        int i = idx >> 6, j = idx & 63;
        float dx = __fadd_rn(xca[j][0], -xca[i][0]);
        float dy = __fadd_rn(xca[j][1], -xca[i][1]);
        float dz = __fadd_rn(xca[j][2], -xca[i][2]);
        float s = __fadd_rn(__fadd_rn(__fmul_rn(dx, dx), __fmul_rn(dy, dy)), __fmul_rn(dz, dz));
        D[i][j] = __fmul_rn(__fmul_rn(msk[j], msk[i]), sqrtf(__fadd_rn(s, 1e-6f)));
    }
    __syncthreads();

    int w = tid >> 5, l = tid & 31;
    for (int i = w; i < 64; i += 8) {
        float m = fmaxf(D[i][l], D[i][l + 32]);
        #pragma unroll
        for (int o = 16; o; o >>= 1) m = fmaxf(m, __shfl_xor_sync(0xffffffffu, m, o));
        if (l == 0) dmax[i] = m + 1.0f;
    }
    __syncthreads();

    // D_adjust = D + (1 - m2) * D_max
    for (int idx = tid; idx < 4096; idx += 256) {
        int i = idx >> 6, j = idx & 63;
        float m2 = __fmul_rn(msk[j], msk[i]);
        D[i][j] = __fadd_rn(D[i][j], __fmul_rn(1.0f - m2, dmax[i]));
    }
    __syncthreads();

    // stable argsort via rank counting (exact match to stable sort tie-break)
    for (int idx = tid; idx < 4096; idx += 256) {
        int i = idx >> 6, j = idx & 63;
        float my = D[i][j];
        int rank = 0;
        #pragma unroll 16
        for (int k = 0; k < 64; k++) {
            float dk = D[i][k];
            rank += (int)(dk < my) | ((int)(dk == my) & (int)(k < j));
        }
        eidx[i][rank] = j;
    }
    __syncthreads();

    size_t base = (size_t)bt * 4096;
    for (int idx = tid; idx < 4096; idx += 256) {
        int i = idx >> 6;
        int j = eidx[i][idx & 63];
        int a = foc[j];
        g_nbr[base + idx] = j;
        g_abs[base + idx] = a;
        g_dnb[base + idx] = D[i][j];
        out[OFF_EI + base + idx] = (float)j;
        out[OFF_AB + base + idx] = (float)a;
    }
}

// ---------------------------------------------------------------------------
// Kernel B: edge features + edge GVP + LN.  Warp-per-edge, lane = channel h.
//   s_out[h] = C(h) + sum_{k<16} RBF_k * W[k][h] + sum_{k<16} Epos_k * W[16+k][h]
// where C folds bias + the vn-half contraction (|dir|^2 == 1 or 0 exactly).
//   v_out[c][h] = dir_c * (wh @ wv)[h]
// ---------------------------------------------------------------------------
__global__ __launch_bounds__(256) void edge_kernel(
    const float* __restrict__ X, const int* __restrict__ chain, int L,
    const float* __restrict__ e_wh,  const float* __restrict__ e_wsw,
    const float* __restrict__ e_wsb, const float* __restrict__ e_wv,
    const float* __restrict__ lng,   const float* __restrict__ lnb,
    float* __restrict__ out)
{
    int bt = blockIdx.x >> 2;
    int q  = blockIdx.x & 3;
    int b  = bt >> 6;
    int tid = threadIdx.x, w = tid >> 5, l = tid & 31;

    __shared__ float xca[64][3];
    __shared__ int   chain0[64];
    __shared__ __align__(16) float sbuf[8][32];

    const size_t ebase = (size_t)bt * 4096;
    for (int idx = tid; idx < 192; idx += 256) {
        int i = idx / 3, c = idx - i * 3;
        xca[i][c] = X[(size_t)(bt * 64 + i) * 12 + 3 + c];
    }
    const int* chainB = chain + b * L;
    if (tid < 64) chain0[tid] = chainB[g_abs[ebase + (size_t)tid * 64]];
    __syncthreads();

    // per-lane weight column in registers (rows 0..31 of ws_w)
    float wreg[32];
    #pragma unroll
    for (int k = 0; k < 32; k++) wreg[k] = e_wsw[k * 32 + l];

    // fold the vn-half of the contraction + v_out projection
    float vnc = 0.f, selfc = 0.f, whv = 0.f;
    #pragma unroll
    for (int m = 0; m < 32; m++) {
        float whm = e_wh[m];
        float wsv = e_wsw[(32 + m) * 32 + l];
        vnc   = fmaf(sqrtf(fmaf(whm, whm, 1e-8f)), wsv, vnc);  // |dir|=1 case
        selfc = fmaf(sqrtf(1e-8f), wsv, selfc);                // dir==0 case
        whv   = fmaf(whm, e_wv[m * 32 + l], whv);
    }
    float bias  = e_wsb[l];
    float baseC = bias + vnc;
    float selfC = bias + selfc;
    float lg = lng[l], lb = lnb[l];

    int e0 = q * 1024 + w * 128;
    for (int t = 0; t < 128; t++) {
        int e = e0 + t;
        int i = e >> 6;
        size_t ge = ebase + e;
        int   nbr = g_nbr[ge];
        float dn  = g_dnb[ge];
        int   an  = g_abs[ge];

        float dx = xca[nbr][0] - xca[i][0];
        float dy = xca[nbr][1] - xca[i][1];
        float dz = xca[nbr][2] - xca[i][2];
        float n2 = dx * dx + dy * dy + dz * dz;
        float invn = 1.0f / fmaxf(sqrtf(n2), 1e-12f);
        float ux = dx * invn, uy = dy * invn, uz = dz * invn;

        float sval;
        if (l < 16) {
            float tt = (dn - (float)l * (20.0f / 15.0f)) * 0.8f;
            sval = __expf(-tt * tt);
        } else {
            int same = (chainB[an] == chain0[i]);
            float tv = g_postab[(an - i + 63) * 16 + (l - 16)];
            sval = same ? tv : 0.0f;
        }
        sbuf[w][l] = sval;
        __syncwarp();

        float acc = (n2 == 0.0f) ? selfC : baseC;
        #pragma unroll
        for (int k = 0; k < 32; k += 4) {
            float4 s4 = *reinterpret_cast<const float4*>(&sbuf[w][k]);
            acc = fmaf(s4.x, wreg[k],     acc);
            acc = fmaf(s4.y, wreg[k + 1], acc);
            acc = fmaf(s4.z, wreg[k + 2], acc);
            acc = fmaf(s4.w, wreg[k + 3], acc);
        }
        __syncwarp();

        // LayerNorm over 32 channels
        float ssum = acc;
        #pragma unroll
        for (int o = 16; o; o >>= 1) ssum += __shfl_xor_sync(0xffffffffu, ssum, o);
        float mean = ssum * (1.0f / 32.0f);
        float dv = acc - mean;
        float vs = dv * dv;
        #pragma unroll
        for (int o = 16; o; o >>= 1) vs += __shfl_xor_sync(0xffffffffu, vs, o);
        float so = dv / sqrtf(vs * (1.0f / 32.0f) + 1e-5f) * lg + lb;

        size_t eb = OFF_E + ge * 128;
        out[eb + l]      = ux * whv;
        out[eb + 32 + l] = uy * whv;
        out[eb + 64 + l] = uz * whv;
        out[eb + 96 + l] = so;
    }
}

// ---------------------------------------------------------------------------
// Kernel C: node geometry (dihedrals / orientations / sidechain vec) + node GVP.
// Phase 1: thread-per-node scalars.  Phase 2: warp-per-node GVP (h = lane, lane+32).
// ---------------------------------------------------------------------------
__device__ __forceinline__ void nrm3(float& x, float& y, float& z) {
    float n = sqrtf(x * x + y * y + z * z);
    float inv = 1.0f / fmaxf(n, 1e-12f);
    x *= inv; y *= inv; z *= inv;
}

__global__ __launch_bounds__(256) void node_kernel(
    const float* __restrict__ X,
    const float* __restrict__ n_wh,  const float* __restrict__ n_wsw,
    const float* __restrict__ n_wsb, const float* __restrict__ n_wv,
    const float* __restrict__ lng,   const float* __restrict__ lnb,
    float* __restrict__ out)
{
    int bt = blockIdx.x;
    int tid = threadIdx.x, w = tid >> 5, l = tid & 31;

    __shared__ float wsw[70 * 64];
    __shared__ float whs[3 * 64];
    __shared__ float whvs[3 * 64];
    __shared__ float wsb[64], glng[64], glnb[64];
    __shared__ float sdi[64][6];
    __shared__ float vmat[64][9];       // [node][c*3 + m]  m: 0=vec 1=fwd 2=bwd
    __shared__ __align__(16) float vnbuf[8][64];

    for (int idx = tid; idx < 4480; idx += 256) wsw[idx] = n_wsw[idx];
    for (int idx = tid; idx < 192; idx += 256)  whs[idx] = n_wh[idx];
    if (tid < 64) { wsb[tid] = n_wsb[tid]; glng[tid] = lng[tid]; glnb[tid] = lnb[tid]; }

    if (tid < 64) {
        int i = tid;
        const float* Xr = X + ((size_t)bt * 64 + i) * 12;
        float nx = Xr[0], ny = Xr[1],  nz = Xr[2];
        float ox = Xr[3], oy = Xr[4],  oz = Xr[5];
        float cx = Xr[6], cy = Xr[7],  cz = Xr[8];
        // sidechain direction
        float ccx = cx - ox, ccy = cy - oy, ccz = cz - oz; nrm3(ccx, ccy, ccz);
        float nnx = nx - ox, nny = ny - oy, nnz = nz - oz; nrm3(nnx, nny, nnz);
        float bx = ccx + nnx, by = ccy + nny, bz = ccz + nnz; nrm3(bx, by, bz);
        float px = ccy * nnz - ccz * nny;
        float py = ccz * nnx - ccx * nnz;
        float pz = ccx * nny - ccy * nnx; nrm3(px, py, pz);
        const float k1 = 0.57735026918962576f, k2 = 0.81649658092772603f;
        vmat[i][0 * 3 + 0] = -bx * k1 - px * k2;
        vmat[i][1 * 3 + 0] = -by * k1 - py * k2;
        vmat[i][2 * 3 + 0] = -bz * k1 - pz * k2;
        // fwd
        float fx = 0.f, fy = 0.f, fz = 0.f;
        if (i < 63) {
            const float* Xn2 = X + ((size_t)bt * 64 + i + 1) * 12 + 3;
            fx = Xn2[0] - ox; fy = Xn2[1] - oy; fz = Xn2[2] - oz; nrm3(fx, fy, fz);
        }
        vmat[i][0 * 3 + 1] = fx; vmat[i][1 * 3 + 1] = fy; vmat[i][2 * 3 + 1] = fz;
        // bwd
        float gx = 0.f, gy = 0.f, gz = 0.f;
        if (i > 0) {
            const float* Xp = X + ((size_t)bt * 64 + i - 1) * 12 + 3;
            gx = ox - Xp[0]; gy = oy - Xp[1]; gz = oz - Xp[2]; nrm3(gx, gy, gz);
            gx = -gx; gy = -gy; gz = -gz;
        }
        vmat[i][0 * 3 + 2] = gx; vmat[i][1 * 3 + 2] = gy; vmat[i][2 * 3 + 2] = gz;
        // dihedrals
        const float* Xbt = X + (size_t)bt * 768;
        for (int t = 0; t < 3; t++) {
            int r = 3 * i + t - 1;
            float ang = 0.0f;
            if (r >= 0 && r < 189) {
                float P[4][3];
                #pragma unroll
                for (int qq = 0; qq < 4; qq++) {
                    int p = r + qq;
                    const float* A = Xbt + (p / 3) * 12 + (p % 3) * 3;
                    P[qq][0] = A[0]; P[qq][1] = A[1]; P[qq][2] = A[2];
                }
                float u2x = P[1][0] - P[0][0], u2y = P[1][1] - P[0][1], u2z = P[1][2] - P[0][2];
                float u1x = P[2][0] - P[1][0], u1y = P[2][1] - P[1][1], u1z = P[2][2] - P[1][2];
                float u0x = P[3][0] - P[2][0], u0y = P[3][1] - P[2][1], u0z = P[3][2] - P[2][2];
                nrm3(u2x, u2y, u2z); nrm3(u1x, u1y, u1z); nrm3(u0x, u0y, u0z);
                float ax = u2y * u1z - u2z * u1y;
                float ay = u2z * u1x - u2x * u1z;
                float az = u2x * u1y - u2y * u1x; nrm3(ax, ay, az);
                float bx_ = u1y * u0z - u1z * u0y;
                float by_ = u1z * u0x - u1x * u0z;
                float bz_ = u1x * u0y - u1y * u0x; nrm3(bx_, by_, bz_);
                float cd = ax * bx_ + ay * by_ + az * bz_;
                cd = fminf(fmaxf(cd, -1.0f + 1e-7f), 1.0f - 1e-7f);
                float sg = u2x * bx_ + u2y * by_ + u2z * bz_;
                float sn = (sg > 0.f) ? 1.f : ((sg < 0.f) ? -1.f : 0.f);
                ang = sn * acosf(cd);
            }
            sdi[i][t]     = cosf(ang);
            sdi[i][3 + t] = sinf(ang);
        }
    }
    __syncthreads();

    // whv = wh @ wv  (3 x 64)
    for (int idx = tid; idx < 192; idx += 256) {
        int p = idx >> 6, h = idx & 63;
        float a = 0.f;
        for (int m = 0; m < 64; m++) a = fmaf(whs[p * 64 + m], n_wv[m * 64 + h], a);
        whvs[idx] = a;
    }
    __syncthreads();

    for (int nd = w; nd < 64; nd += 8) {
        float vm[9];
        #pragma unroll
        for (int z = 0; z < 9; z++) vm[z] = vmat[nd][z];
        int h0 = l, h1 = l + 32;
        float vh0[3], vh1[3];
        #pragma unroll
        for (int c = 0; c < 3; c++) {
            vh0[c] = vm[c * 3 + 0] * whs[0 * 64 + h0] + vm[c * 3 + 1] * whs[1 * 64 + h0] + vm[c * 3 + 2] * whs[2 * 64 + h0];
            vh1[c] = vm[c * 3 + 0] * whs[0 * 64 + h1] + vm[c * 3 + 1] * whs[1 * 64 + h1] + vm[c * 3 + 2] * whs[2 * 64 + h1];
        }
        float vn0 = sqrtf(vh0[0] * vh0[0] + vh0[1] * vh0[1] + vh0[2] * vh0[2] + 1e-8f);
        float vn1 = sqrtf(vh1[0] * vh1[0] + vh1[1] * vh1[1] + vh1[2] * vh1[2] + 1e-8f);
        vnbuf[w][l] = vn0; vnbuf[w][l + 32] = vn1;
        __syncwarp();

        float acc0 = wsb[h0], acc1 = wsb[h1];
        #pragma unroll
        for (int k = 0; k < 6; k++) {
            float dk = sdi[nd][k];
            acc0 = fmaf(dk, wsw[k * 64 + h0], acc0);
            acc1 = fmaf(dk, wsw[k * 64 + h1], acc1);
        }
        #pragma unroll
        for (int m = 0; m < 64; m += 4) {
            float4 v4 = *reinterpret_cast<const float4*>(&vnbuf[w][m]);
            acc0 = fmaf(v4.x, wsw[(6 + m) * 64 + h0], acc0);
            acc1 = fmaf(v4.x, wsw[(6 + m) * 64 + h1], acc1);
            acc0 = fmaf(v4.y, wsw[(7 + m) * 64 + h0], acc0);
            acc1 = fmaf(v4.y, wsw[(7 + m) * 64 + h1], acc1);
            acc0 = fmaf(v4.z, wsw[(8 + m) * 64 + h0], acc0);
            acc1 = fmaf(v4.z, wsw[(8 + m) * 64 + h1], acc1);
            acc0 = fmaf(v4.w, wsw[(9 + m) * 64 + h0], acc0);
            acc1 = fmaf(v4.w, wsw[(9 + m) * 64 + h1], acc1);
        }
        __syncwarp();

        // LayerNorm over 64 channels (2 per lane)
        float ssum = acc0 + acc1;
        #pragma unroll
        for (int o = 16; o; o >>= 1) ssum += __shfl_xor_sync(0xffffffffu, ssum, o);
        float mean = ssum * (1.0f / 64.0f);
        float d0 = acc0 - mean, d1 = acc1 - mean;
        float vs = d0 * d0 + d1 * d1;
        #pragma unroll
        for (int o = 16; o; o >>= 1) vs += __shfl_xor_sync(0xffffffffu, vs, o);
        float inv = 1.0f / sqrtf(vs * (1.0f / 64.0f) + 1e-5f);
        float o0 = d0 * inv * glng[h0] + glnb[h0];
        float o1 = d1 * inv * glng[h1] + glnb[h1];

        size_t vb = ((size_t)bt * 64 + nd) * 256;
        #pragma unroll
        for (int c = 0; c < 3; c++) {
            float vo0 = vm[c * 3 + 0] * whvs[0 * 64 + h0] + vm[c * 3 + 1] * whvs[1 * 64 + h0] + vm[c * 3 + 2] * whvs[2 * 64 + h0];
            float vo1 = vm[c * 3 + 0] * whvs[0 * 64 + h1] + vm[c * 3 + 1] * whvs[1 * 64 + h1] + vm[c * 3 + 2] * whvs[2 * 64 + h1];
            out[vb + c * 64 + h0] = vo0;
            out[vb + c * 64 + h1] = vo1;
        }
        out[vb + 192 + h0] = o0;
        out[vb + 192 + h1] = o1;
    }
}

// ---------------------------------------------------------------------------
extern "C" void kernel_launch(void* const* d_in, const int* in_sizes, int n_in,
                              void* d_out, int out_size)
{
    const float* X      = (const float*)d_in[0];
    const float* mask   = (const float*)d_in[1];
    const int*   chain  = (const int*)d_in[2];
    const int*   focus  = (const int*)d_in[3];
    const float* n_wh   = (const float*)d_in[4];
    const float* n_wsw  = (const float*)d_in[5];
    const float* n_wsb  = (const float*)d_in[6];
    const float* n_wv   = (const float*)d_in[7];
    const float* e_wh   = (const float*)d_in[8];
    const float* e_wsw  = (const float*)d_in[9];
    const float* e_wsb  = (const float*)d_in[10];
    const float* e_wv   = (const float*)d_in[11];
    const float* ln_n_g = (const float*)d_in[12];
    const float* ln_n_b = (const float*)d_in[13];
    const float* ln_e_g = (const float*)d_in[14];
    const float* ln_e_b = (const float*)d_in[15];
    float* out = (float*)d_out;
    int L = in_sizes[2] / B_;

    init_postab_kernel<<<36, 256>>>();
    sort_kernel<<<BT, 256>>>(X, mask, focus, out);
    edge_kernel<<<BT * 4, 256>>>(X, chain, L, e_wh, e_wsw, e_wsb, e_wv, ln_e_g, ln_e_b, out);
    node_kernel<<<BT, 256>>>(X, n_wh, n_wsw, n_wsb, n_wv, ln_n_g, ln_n_b, out);
}

// round 2
// speedup vs baseline: 1.0064x; 1.0064x over previous
#include <cuda_runtime.h>
#include <math.h>

// Problem constants
#define B_  2
#define T_  64
#define N_  64
#define BT  128                      // B*T
#define NEDGE (BT * N_ * N_)         // 524288
#define V_SZ  ((size_t)BT * N_ * 256)       // 2097152
#define E_SZ  ((size_t)NEDGE * 128)         // 67108864
#define OFF_E  (V_SZ)
#define OFF_EI (OFF_E + E_SZ)               // 69206016
#define OFF_AB (OFF_EI + (size_t)NEDGE)     // 69730304

// Scratch (allowed: __device__ globals)
__device__ int   g_nbr[NEDGE];
__device__ int   g_abs[NEDGE];
__device__ float g_dnb[NEDGE];
__device__ float g_postab[575 * 16];

// ---------------------------------------------------------------------------
// Positional-encoding table: d in [-63, 511] -> 16 values [cos(d*f0..f7), sin(...)]
// Built with accurate cosf/sinf (args up to ~511 rad: __cosf would be too lossy).
// ---------------------------------------------------------------------------
__global__ void init_postab_kernel() {
    int idx = blockIdx.x * blockDim.x + threadIdx.x;
    if (idx >= 575 * 16) return;
    int dpos = idx >> 4;
    int k = idx & 15;
    float d = (float)(dpos - 63);
    int j = k & 7;
    float fr = expf((float)(2 * j) * (float)(-0.5756462732485114)); // -ln(1e4)/16
    float ang = d * fr;
    g_postab[idx] = (k < 8) ? cosf(ang) : sinf(ang);
}

// ---------------------------------------------------------------------------
// Kernel A: per (b,t) distance matrix + exact stable argsort (rank counting).
// Writes E_idx / abs_E_idx (float) straight into d_out + int/float scratch.
// ---------------------------------------------------------------------------
__global__ __launch_bounds__(256) void sort_kernel(
    const float* __restrict__ X, const float* __restrict__ mask,
    const int* __restrict__ focus, float* __restrict__ out)
{
    int bt = blockIdx.x;
    int tid = threadIdx.x;
    __shared__ float xca[64][3];
    __shared__ float msk[64];
    __shared__ float D[64][65];
    __shared__ float dmax[64];
    __shared__ int   eidx[64][64];
    __shared__ int   foc[64];

    for (int idx = tid; idx < 192; idx += 256) {
        int i = idx / 3, c = idx - i * 3;
        xca[i][c] = X[(size_t)(bt * 64 + i) * 12 + 3 + c];   // atom 1 = CA
    }
    for (int i = tid; i < 64; i += 256) {
        msk[i] = mask[bt * 64 + i];
        foc[i] = focus[bt * 64 + i];
    }
    __syncthreads();

    // D = mask2d * sqrt(|dX|^2 + 1e-6)  (non-contracted to match XLA rounding)
    for (int idx = tid; idx < 4096; idx += 256) {
        int i = idx >> 6, j = idx & 63;
        float dx = __fadd_rn(xca[j][0], -xca[i][0]);
        float dy = __fadd_rn(xca[j][1], -xca[i][1]);
        float dz = __fadd_rn(xca[j][2], -xca[i][2]);
        float s = __fadd_rn(__fadd_rn(__fmul_rn(dx, dx), __fmul_rn(dy, dy)), __fmul_rn(dz, dz));
        D[i][j] = __fmul_rn(__fmul_rn(msk[j], msk[i]), sqrtf(__fadd_rn(s, 1e-6f)));
    }
    __syncthreads();

    int w = tid >> 5, l = tid & 31;
    for (int i = w; i < 64; i += 8) {
        float m = fmaxf(D[i][l], D[i][l + 32]);
        #pragma unroll
        for (int o = 16; o; o >>= 1) m = fmaxf(m, __shfl_xor_sync(0xffffffffu, m, o));
        if (l == 0) dmax[i] = m + 1.0f;
    }
    __syncthreads();

    // D_adjust = D + (1 - m2) * D_max
    for (int idx = tid; idx < 4096; idx += 256) {
        int i = idx >> 6, j = idx & 63;
        float m2 = __fmul_rn(msk[j], msk[i]);
        D[i][j] = __fadd_rn(D[i][j], __fmul_rn(1.0f - m2, dmax[i]));
    }
    __syncthreads();

    // stable argsort via rank counting (exact match to stable sort tie-break)
    for (int idx = tid; idx < 4096; idx += 256) {
        int i = idx >> 6, j = idx & 63;
        float my = D[i][j];
        int rank = 0;
        #pragma unroll 16
        for (int k = 0; k < 64; k++) {
            float dk = D[i][k];
            rank += (int)(dk < my) | ((int)(dk == my) & (int)(k < j));
        }
        eidx[i][rank] = j;
    }
    __syncthreads();

    size_t base = (size_t)bt * 4096;
    for (int idx = tid; idx < 4096; idx += 256) {
        int i = idx >> 6;
        int j = eidx[i][idx & 63];
        int a = foc[j];
        g_nbr[base + idx] = j;
        g_abs[base + idx] = a;
        g_dnb[base + idx] = D[i][j];
        out[OFF_EI + base + idx] = (float)j;
        out[OFF_AB + base + idx] = (float)a;
    }
}

// ---------------------------------------------------------------------------
// Kernel B: edge features + edge GVP + LN.  Warp-per-edge, lane = channel h.
//   s_out[h] = C(h) + sum_{k<16} RBF_k * W[k][h] + sum_{k<16} Epos_k * W[16+k][h]
// where C folds bias + the vn-half contraction (|dir|^2 == 1 or 0 exactly).
//   v_out[c][h] = dir_c * (wh @ wv)[h]
// ---------------------------------------------------------------------------
__global__ __launch_bounds__(256) void edge_kernel(
    const float* __restrict__ X, const int* __restrict__ chain, int L,
    const float* __restrict__ e_wh,  const float* __restrict__ e_wsw,
    const float* __restrict__ e_wsb, const float* __restrict__ e_wv,
    const float* __restrict__ lng,   const float* __restrict__ lnb,
    float* __restrict__ out)
{
    int bt = blockIdx.x >> 2;
    int q  = blockIdx.x & 3;
    int b  = bt >> 6;
    int tid = threadIdx.x, w = tid >> 5, l = tid & 31;

    __shared__ float xca[64][3];
    __shared__ int   chain0[64];
    __shared__ __align__(16) float sbuf[8][32];

    const size_t ebase = (size_t)bt * 4096;
    for (int idx = tid; idx < 192; idx += 256) {
        int i = idx / 3, c = idx - i * 3;
        xca[i][c] = X[(size_t)(bt * 64 + i) * 12 + 3 + c];
    }
    const int* chainB = chain + b * L;
    if (tid < 64) chain0[tid] = chainB[g_abs[ebase + (size_t)tid * 64]];
    __syncthreads();

    // per-lane weight column in registers (rows 0..31 of ws_w)
    float wreg[32];
    #pragma unroll
    for (int k = 0; k < 32; k++) wreg[k] = e_wsw[k * 32 + l];

    // fold the vn-half of the contraction + v_out projection
    float vnc = 0.f, selfc = 0.f, whv = 0.f;
    #pragma unroll
    for (int m = 0; m < 32; m++) {
        float whm = e_wh[m];
        float wsv = e_wsw[(32 + m) * 32 + l];
        vnc   = fmaf(sqrtf(fmaf(whm, whm, 1e-8f)), wsv, vnc);  // |dir|=1 case
        selfc = fmaf(sqrtf(1e-8f), wsv, selfc);                // dir==0 case
        whv   = fmaf(whm, e_wv[m * 32 + l], whv);
    }
    float bias  = e_wsb[l];
    float baseC = bias + vnc;
    float selfC = bias + selfc;
    float lg = lng[l], lb = lnb[l];

    int e0 = q * 1024 + w * 128;
    for (int t = 0; t < 128; t++) {
        int e = e0 + t;
        int i = e >> 6;
        size_t ge = ebase + e;
        int   nbr = g_nbr[ge];
        float dn  = g_dnb[ge];
        int   an  = g_abs[ge];

        float dx = xca[nbr][0] - xca[i][0];
        float dy = xca[nbr][1] - xca[i][1];
        float dz = xca[nbr][2] - xca[i][2];
        float n2 = dx * dx + dy * dy + dz * dz;
        float invn = 1.0f / fmaxf(sqrtf(n2), 1e-12f);
        float ux = dx * invn, uy = dy * invn, uz = dz * invn;

        float sval;
        if (l < 16) {
            float tt = (dn - (float)l * (20.0f / 15.0f)) * 0.8f;
            sval = __expf(-tt * tt);
        } else {
            int same = (chainB[an] == chain0[i]);
            float tv = g_postab[(an - i + 63) * 16 + (l - 16)];
            sval = same ? tv : 0.0f;
        }
        sbuf[w][l] = sval;
        __syncwarp();

        float acc = (n2 == 0.0f) ? selfC : baseC;
        #pragma unroll
        for (int k = 0; k < 32; k += 4) {
            float4 s4 = *reinterpret_cast<const float4*>(&sbuf[w][k]);
            acc = fmaf(s4.x, wreg[k],     acc);
            acc = fmaf(s4.y, wreg[k + 1], acc);
            acc = fmaf(s4.z, wreg[k + 2], acc);
            acc = fmaf(s4.w, wreg[k + 3], acc);
        }
        __syncwarp();

        // LayerNorm over 32 channels
        float ssum = acc;
        #pragma unroll
        for (int o = 16; o; o >>= 1) ssum += __shfl_xor_sync(0xffffffffu, ssum, o);
        float mean = ssum * (1.0f / 32.0f);
        float dv = acc - mean;
        float vs = dv * dv;
        #pragma unroll
        for (int o = 16; o; o >>= 1) vs += __shfl_xor_sync(0xffffffffu, vs, o);
        float so = dv / sqrtf(vs * (1.0f / 32.0f) + 1e-5f) * lg + lb;

        size_t eb = OFF_E + ge * 128;
        out[eb + l]      = ux * whv;
        out[eb + 32 + l] = uy * whv;
        out[eb + 64 + l] = uz * whv;
        out[eb + 96 + l] = so;
    }
}

// ---------------------------------------------------------------------------
// Kernel C: node geometry (dihedrals / orientations / sidechain vec) + node GVP.
// Phase 1: thread-per-node scalars.  Phase 2: warp-per-node GVP (h = lane, lane+32).
// ---------------------------------------------------------------------------
__device__ __forceinline__ void nrm3(float& x, float& y, float& z) {
    float n = sqrtf(x * x + y * y + z * z);
    float inv = 1.0f / fmaxf(n, 1e-12f);
    x *= inv; y *= inv; z *= inv;
}

__global__ __launch_bounds__(256) void node_kernel(
    const float* __restrict__ X,
    const float* __restrict__ n_wh,  const float* __restrict__ n_wsw,
    const float* __restrict__ n_wsb, const float* __restrict__ n_wv,
    const float* __restrict__ lng,   const float* __restrict__ lnb,
    float* __restrict__ out)
{
    int bt = blockIdx.x;
    int tid = threadIdx.x, w = tid >> 5, l = tid & 31;

    __shared__ float wsw[70 * 64];
    __shared__ float whs[3 * 64];
    __shared__ float whvs[3 * 64];
    __shared__ float wsb[64], glng[64], glnb[64];
    __shared__ float sdi[64][6];
    __shared__ float vmat[64][9];       // [node][c*3 + m]  m: 0=vec 1=fwd 2=bwd
    __shared__ __align__(16) float vnbuf[8][64];

    for (int idx = tid; idx < 4480; idx += 256) wsw[idx] = n_wsw[idx];
    for (int idx = tid; idx < 192; idx += 256)  whs[idx] = n_wh[idx];
    if (tid < 64) { wsb[tid] = n_wsb[tid]; glng[tid] = lng[tid]; glnb[tid] = lnb[tid]; }

    if (tid < 64) {
        int i = tid;
        const float* Xr = X + ((size_t)bt * 64 + i) * 12;
        float nx = Xr[0], ny = Xr[1],  nz = Xr[2];
        float ox = Xr[3], oy = Xr[4],  oz = Xr[5];
        float cx = Xr[6], cy = Xr[7],  cz = Xr[8];
        // sidechain direction
        float ccx = cx - ox, ccy = cy - oy, ccz = cz - oz; nrm3(ccx, ccy, ccz);
        float nnx = nx - ox, nny = ny - oy, nnz = nz - oz; nrm3(nnx, nny, nnz);
        float bx = ccx + nnx, by = ccy + nny, bz = ccz + nnz; nrm3(bx, by, bz);
        float px = ccy * nnz - ccz * nny;
        float py = ccz * nnx - ccx * nnz;
        float pz = ccx * nny - ccy * nnx; nrm3(px, py, pz);
        const float k1 = 0.57735026918962576f, k2 = 0.81649658092772603f;
        vmat[i][0 * 3 + 0] = -bx * k1 - px * k2;
        vmat[i][1 * 3 + 0] = -by * k1 - py * k2;
        vmat[i][2 * 3 + 0] = -bz * k1 - pz * k2;
        // fwd
        float fx = 0.f, fy = 0.f, fz = 0.f;
        if (i < 63) {
            const float* Xn2 = X + ((size_t)bt * 64 + i + 1) * 12 + 3;
            fx = Xn2[0] - ox; fy = Xn2[1] - oy; fz = Xn2[2] - oz; nrm3(fx, fy, fz);
        }
        vmat[i][0 * 3 + 1] = fx; vmat[i][1 * 3 + 1] = fy; vmat[i][2 * 3 + 1] = fz;
        // bwd
        float gx = 0.f, gy = 0.f, gz = 0.f;
        if (i > 0) {
            const float* Xp = X + ((size_t)bt * 64 + i - 1) * 12 + 3;
            gx = ox - Xp[0]; gy = oy - Xp[1]; gz = oz - Xp[2]; nrm3(gx, gy, gz);
            gx = -gx; gy = -gy; gz = -gz;
        }
        vmat[i][0 * 3 + 2] = gx; vmat[i][1 * 3 + 2] = gy; vmat[i][2 * 3 + 2] = gz;
        // dihedrals
        const float* Xbt = X + (size_t)bt * 768;
        for (int t = 0; t < 3; t++) {
            int r = 3 * i + t - 1;
            float ang = 0.0f;
            if (r >= 0 && r < 189) {
                float P[4][3];
                #pragma unroll
                for (int qq = 0; qq < 4; qq++) {
                    int p = r + qq;
                    const float* A = Xbt + (p / 3) * 12 + (p % 3) * 3;
                    P[qq][0] = A[0]; P[qq][1] = A[1]; P[qq][2] = A[2];
                }
                float u2x = P[1][0] - P[0][0], u2y = P[1][1] - P[0][1], u2z = P[1][2] - P[0][2];
                float u1x = P[2][0] - P[1][0], u1y = P[2][1] - P[1][1], u1z = P[2][2] - P[1][2];
                float u0x = P[3][0] - P[2][0], u0y = P[3][1] - P[2][1], u0z = P[3][2] - P[2][2];
                nrm3(u2x, u2y, u2z); nrm3(u1x, u1y, u1z); nrm3(u0x, u0y, u0z);
                float ax = u2y * u1z - u2z * u1y;
                float ay = u2z * u1x - u2x * u1z;
                float az = u2x * u1y - u2y * u1x; nrm3(ax, ay, az);
                float bx_ = u1y * u0z - u1z * u0y;
                float by_ = u1z * u0x - u1x * u0z;
                float bz_ = u1x * u0y - u1y * u0x; nrm3(bx_, by_, bz_);
                float cd = ax * bx_ + ay * by_ + az * bz_;
                cd = fminf(fmaxf(cd, -1.0f + 1e-7f), 1.0f - 1e-7f);
                float sg = u2x * bx_ + u2y * by_ + u2z * bz_;
                float sn = (sg > 0.f) ? 1.f : ((sg < 0.f) ? -1.f : 0.f);
                ang = sn * acosf(cd);
            }
            sdi[i][t]     = cosf(ang);
            sdi[i][3 + t] = sinf(ang);
        }
    }
    __syncthreads();

    // whv = wh @ wv  (3 x 64)
    for (int idx = tid; idx < 192; idx += 256) {
        int p = idx >> 6, h = idx & 63;
        float a = 0.f;
        for (int m = 0; m < 64; m++) a = fmaf(whs[p * 64 + m], n_wv[m * 64 + h], a);
        whvs[idx] = a;
    }
    __syncthreads();

    for (int nd = w; nd < 64; nd += 8) {
        float vm[9];
        #pragma unroll
        for (int z = 0; z < 9; z++) vm[z] = vmat[nd][z];
        int h0 = l, h1 = l + 32;
        float vh0[3], vh1[3];
        #pragma unroll
        for (int c = 0; c < 3; c++) {
            vh0[c] = vm[c * 3 + 0] * whs[0 * 64 + h0] + vm[c * 3 + 1] * whs[1 * 64 + h0] + vm[c * 3 + 2] * whs[2 * 64 + h0];
            vh1[c] = vm[c * 3 + 0] * whs[0 * 64 + h1] + vm[c * 3 + 1] * whs[1 * 64 + h1] + vm[c * 3 + 2] * whs[2 * 64 + h1];
        }
        float vn0 = sqrtf(vh0[0] * vh0[0] + vh0[1] * vh0[1] + vh0[2] * vh0[2] + 1e-8f);
        float vn1 = sqrtf(vh1[0] * vh1[0] + vh1[1] * vh1[1] + vh1[2] * vh1[2] + 1e-8f);
        vnbuf[w][l] = vn0; vnbuf[w][l + 32] = vn1;
        __syncwarp();

        float acc0 = wsb[h0], acc1 = wsb[h1];
        #pragma unroll
        for (int k = 0; k < 6; k++) {
            float dk = sdi[nd][k];
            acc0 = fmaf(dk, wsw[k * 64 + h0], acc0);
            acc1 = fmaf(dk, wsw[k * 64 + h1], acc1);
        }
        #pragma unroll
        for (int m = 0; m < 64; m += 4) {
            float4 v4 = *reinterpret_cast<const float4*>(&vnbuf[w][m]);
            acc0 = fmaf(v4.x, wsw[(6 + m) * 64 + h0], acc0);
            acc1 = fmaf(v4.x, wsw[(6 + m) * 64 + h1], acc1);
            acc0 = fmaf(v4.y, wsw[(7 + m) * 64 + h0], acc0);
            acc1 = fmaf(v4.y, wsw[(7 + m) * 64 + h1], acc1);
            acc0 = fmaf(v4.z, wsw[(8 + m) * 64 + h0], acc0);
            acc1 = fmaf(v4.z, wsw[(8 + m) * 64 + h1], acc1);
            acc0 = fmaf(v4.w, wsw[(9 + m) * 64 + h0], acc0);
            acc1 = fmaf(v4.w, wsw[(9 + m) * 64 + h1], acc1);
        }
        __syncwarp();

        // LayerNorm over 64 channels (2 per lane)
        float ssum = acc0 + acc1;
        #pragma unroll
        for (int o = 16; o; o >>= 1) ssum += __shfl_xor_sync(0xffffffffu, ssum, o);
        float mean = ssum * (1.0f / 64.0f);
        float d0 = acc0 - mean, d1 = acc1 - mean;
        float vs = d0 * d0 + d1 * d1;
        #pragma unroll
        for (int o = 16; o; o >>= 1) vs += __shfl_xor_sync(0xffffffffu, vs, o);
        float inv = 1.0f / sqrtf(vs * (1.0f / 64.0f) + 1e-5f);
        float o0 = d0 * inv * glng[h0] + glnb[h0];
        float o1 = d1 * inv * glng[h1] + glnb[h1];

        size_t vb = ((size_t)bt * 64 + nd) * 256;
        #pragma unroll
        for (int c = 0; c < 3; c++) {
            float vo0 = vm[c * 3 + 0] * whvs[0 * 64 + h0] + vm[c * 3 + 1] * whvs[1 * 64 + h0] + vm[c * 3 + 2] * whvs[2 * 64 + h0];
            float vo1 = vm[c * 3 + 0] * whvs[0 * 64 + h1] + vm[c * 3 + 1] * whvs[1 * 64 + h1] + vm[c * 3 + 2] * whvs[2 * 64 + h1];
            out[vb + c * 64 + h0] = vo0;
            out[vb + c * 64 + h1] = vo1;
        }
        out[vb + 192 + h0] = o0;
        out[vb + 192 + h1] = o1;
    }
}

// ---------------------------------------------------------------------------
extern "C" void kernel_launch(void* const* d_in, const int* in_sizes, int n_in,
                              void* d_out, int out_size)
{
    const float* X      = (const float*)d_in[0];
    const float* mask   = (const float*)d_in[1];
    const int*   chain  = (const int*)d_in[2];
    const int*   focus  = (const int*)d_in[3];
    const float* n_wh   = (const float*)d_in[4];
    const float* n_wsw  = (const float*)d_in[5];
    const float* n_wsb  = (const float*)d_in[6];
    const float* n_wv   = (const float*)d_in[7];
    const float* e_wh   = (const float*)d_in[8];
    const float* e_wsw  = (const float*)d_in[9];
    const float* e_wsb  = (const float*)d_in[10];
    const float* e_wv   = (const float*)d_in[11];
    const float* ln_n_g = (const float*)d_in[12];
    const float* ln_n_b = (const float*)d_in[13];
    const float* ln_e_g = (const float*)d_in[14];
    const float* ln_e_b = (const float*)d_in[15];
    float* out = (float*)d_out;
    int L = in_sizes[2] / B_;

    init_postab_kernel<<<36, 256>>>();
    sort_kernel<<<BT, 256>>>(X, mask, focus, out);
    edge_kernel<<<BT * 4, 256>>>(X, chain, L, e_wh, e_wsw, e_wsb, e_wv, ln_e_g, ln_e_b, out);
    node_kernel<<<BT, 256>>>(X, n_wh, n_wsw, n_wsb, n_wv, ln_n_g, ln_n_b, out);
}

// round 3
// speedup vs baseline: 1.8839x; 1.8720x over previous
#include <cuda_runtime.h>
#include <math.h>

// Problem constants
#define BT  128                             // B*T
#define NEDGE (BT * 64 * 64)                // 524288
#define V_SZ  ((size_t)BT * 64 * 256)       // 2097152
#define E_SZ  ((size_t)NEDGE * 128)         // 67108864
#define OFF_E  (V_SZ)
#define OFF_EI (OFF_E + E_SZ)               // 69206016
#define OFF_AB (OFF_EI + (size_t)NEDGE)     // 69730304

#define EDGE_BLOCKS 1024                    // BT * 8
#define NODE_BLOCKS 128                     // BT

__device__ float g_postab[575 * 16];

// ---------------------------------------------------------------------------
// Positional-encoding table: d in [-63, 511] -> [cos(d*f0..f7), sin(...)]
// ---------------------------------------------------------------------------
__global__ void init_postab_kernel() {
    int idx = blockIdx.x * blockDim.x + threadIdx.x;
    if (idx >= 575 * 16) return;
    int dpos = idx >> 4;
    int k = idx & 15;
    float d = (float)(dpos - 63);
    int j = k & 7;
    float fr = expf((float)(2 * j) * (float)(-0.5756462732485114)); // -ln(1e4)/16
    float ang = d * fr;
    g_postab[idx] = (k < 8) ? cosf(ang) : sinf(ang);
}

__device__ __forceinline__ void nrm3(float& x, float& y, float& z) {
    float n = sqrtf(x * x + y * y + z * z);
    float inv = 1.0f / fmaxf(n, 1e-12f);
    x *= inv; y *= inv; z *= inv;
}

// ---------------------------------------------------------------------------
// Mega kernel: blocks [0,1024) = fused sort+edge path, [1024,1152) = node path
// ---------------------------------------------------------------------------
__global__ __launch_bounds__(256) void mega_kernel(
    const float* __restrict__ X, const float* __restrict__ mask,
    const int* __restrict__ chain, const int* __restrict__ focus, int L,
    const float* __restrict__ n_wh,  const float* __restrict__ n_wsw,
    const float* __restrict__ n_wsb, const float* __restrict__ n_wv,
    const float* __restrict__ e_wh,  const float* __restrict__ e_wsw,
    const float* __restrict__ e_wsb, const float* __restrict__ e_wv,
    const float* __restrict__ lnng,  const float* __restrict__ lnnb,
    const float* __restrict__ lneg,  const float* __restrict__ lneb,
    float* __restrict__ out)
{
    __shared__ __align__(16) char smraw[44288];
    int bx = blockIdx.x;
    int tid = threadIdx.x, w = tid >> 5, l = tid & 31;

    if (bx < EDGE_BLOCKS) {
        // ================= EDGE PATH (fused sort + features + GVP + LN) ====
        float* xca  = (float*)smraw;              // 192
        float* msk  = xca + 192;                  // 64
        int*   foc  = (int*)(msk + 64);           // 64
        int*   chs  = foc + 64;                   // 512
        float* Drow = (float*)(chs + 512);        // 8*64
        int*   erow = (int*)(Drow + 512);         // 8*64
        float* feat = (float*)(erow + 512);       // 8*32*36  (16B aligned)

        int bt = bx >> 3, rg = bx & 7, b = bt >> 6;
        const float* Xbt = X + (size_t)bt * 768;
        for (int idx = tid; idx < 192; idx += 256)
            xca[idx] = Xbt[(idx / 3) * 12 + 3 + (idx % 3)];
        if (tid < 64) {
            msk[tid] = mask[bt * 64 + tid];
            foc[tid] = focus[bt * 64 + tid];
        }
        const int* chainB = chain + b * L;
        bool chsm = (L <= 512);
        if (chsm) for (int idx = tid; idx < L; idx += 256) chs[idx] = chainB[idx];
        __syncthreads();

        // per-lane weight column (rows 0..31 of ws_w) + folded constants
        float wreg[32];
        #pragma unroll
        for (int k = 0; k < 32; k++) wreg[k] = e_wsw[k * 32 + l];
        float vnc = 0.f, selfc = 0.f, whv = 0.f;
        #pragma unroll
        for (int m = 0; m < 32; m++) {
            float whm = e_wh[m];
            float wsv = e_wsw[(32 + m) * 32 + l];
            vnc   = fmaf(sqrtf(fmaf(whm, whm, 1e-8f)), wsv, vnc);  // |dir|=1
            selfc = fmaf(sqrtf(1e-8f), wsv, selfc);                // dir==0
            whv   = fmaf(whm, e_wv[m * 32 + l], whv);
        }
        float bias = e_wsb[l];
        float baseC = bias + vnc;
        float dC = selfc - vnc;                 // selfC - baseC
        float lg = lneg[l], lb = lneb[l];

        // ---- per-warp row: distances + stable argsort (rank count) ----
        int i = rg * 8 + w;
        float xix = xca[i * 3], xiy = xca[i * 3 + 1], xiz = xca[i * 3 + 2];
        float mi = msk[i];

        int j0 = l, j1 = l + 32;
        float d0, d1, a0, a1;
        {
            float dx = __fadd_rn(xca[j0 * 3],     -xix);
            float dy = __fadd_rn(xca[j0 * 3 + 1], -xiy);
            float dz = __fadd_rn(xca[j0 * 3 + 2], -xiz);
            float s = __fadd_rn(__fadd_rn(__fmul_rn(dx, dx), __fmul_rn(dy, dy)), __fmul_rn(dz, dz));
            d0 = __fmul_rn(__fmul_rn(msk[j0], mi), sqrtf(__fadd_rn(s, 1e-6f)));
            dx = __fadd_rn(xca[j1 * 3],     -xix);
            dy = __fadd_rn(xca[j1 * 3 + 1], -xiy);
            dz = __fadd_rn(xca[j1 * 3 + 2], -xiz);
            s = __fadd_rn(__fadd_rn(__fmul_rn(dx, dx), __fmul_rn(dy, dy)), __fmul_rn(dz, dz));
            d1 = __fmul_rn(__fmul_rn(msk[j1], mi), sqrtf(__fadd_rn(s, 1e-6f)));
        }
        float mx = fmaxf(d0, d1);
        #pragma unroll
        for (int o = 16; o; o >>= 1) mx = fmaxf(mx, __shfl_xor_sync(0xffffffffu, mx, o));
        float dmax = mx + 1.0f;
        {
            float m20 = __fmul_rn(msk[j0], mi);
            float m21 = __fmul_rn(msk[j1], mi);
            a0 = __fadd_rn(d0, __fmul_rn(1.0f - m20, dmax));
            a1 = __fadd_rn(d1, __fmul_rn(1.0f - m21, dmax));
        }
        Drow[w * 64 + j0] = a0;
        Drow[w * 64 + j1] = a1;
        __syncwarp();
        int r0 = 0, r1 = 0;
        #pragma unroll 16
        for (int k = 0; k < 64; k++) {
            float dk = Drow[w * 64 + k];
            r0 += (int)(dk < a0) | ((int)(dk == a0) & (int)(k < j0));
            r1 += (int)(dk < a1) | ((int)(dk == a1) & (int)(k < j1));
        }
        erow[w * 64 + r0] = j0;
        erow[w * 64 + r1] = j1;
        __syncwarp();

        int nbr0 = erow[w * 64];
        int c0 = chsm ? chs[foc[nbr0]] : chainB[foc[nbr0]];
        size_t gebase = (size_t)bt * 4096 + (size_t)i * 64;
        float4* frl = (float4*)(feat + w * 1152 + l * 36);
        const float4* fw = (const float4*)(feat + w * 1152);

        for (int t2 = 0; t2 < 2; t2++) {
            // ---- phase 1: lane = edge, build 36-float feature row ----
            int e = t2 * 32 + l;
            int nbr = erow[w * 64 + e];
            float dn = Drow[w * 64 + nbr];
            int an = foc[nbr];
            size_t ge = gebase + e;
            out[OFF_EI + ge] = (float)nbr;
            out[OFF_AB + ge] = (float)an;

            float dx = xca[nbr * 3]     - xix;
            float dy = xca[nbr * 3 + 1] - xiy;
            float dz = xca[nbr * 3 + 2] - xiz;
            float n2 = dx * dx + dy * dy + dz * dz;
            float invn = 1.0f / fmaxf(sqrtf(n2), 1e-12f);

            // RBF (16 values, 4 float4s)
            #pragma unroll
            for (int q = 0; q < 4; q++) {
                float4 v;
                float t0 = (dn - (float)(4 * q + 0) * (20.0f / 15.0f)) * 0.8f;
                float t1 = (dn - (float)(4 * q + 1) * (20.0f / 15.0f)) * 0.8f;
                float tA = (dn - (float)(4 * q + 2) * (20.0f / 15.0f)) * 0.8f;
                float tB = (dn - (float)(4 * q + 3) * (20.0f / 15.0f)) * 0.8f;
                v.x = __expf(-t0 * t0); v.y = __expf(-t1 * t1);
                v.z = __expf(-tA * tA); v.w = __expf(-tB * tB);
                frl[q] = v;
            }
            // positional (16 values from table, chain-masked)
            float sf = ((chsm ? chs[an] : chainB[an]) == c0) ? 1.0f : 0.0f;
            const float4* pt = (const float4*)(g_postab + (((an - i) + 63) << 4));
            #pragma unroll
            for (int q = 0; q < 4; q++) {
                float4 p = pt[q];
                float4 v = {p.x * sf, p.y * sf, p.z * sf, p.w * sf};
                frl[4 + q] = v;
            }
            {
                float4 v = {dx * invn, dy * invn, dz * invn, (n2 == 0.0f) ? 1.0f : 0.0f};
                frl[8] = v;
            }
            __syncwarp();

            // ---- phase 2: lane = channel, 2-edge interleaved GVP + LN ----
            size_t eo_base = OFF_E + (gebase + (size_t)(t2 * 32)) * 128;
            for (int t = 0; t < 32; t += 2) {
                const float4* ra = fw + t * 9;
                const float4* rb = ra + 9;
                float4 ga = ra[8], gb = rb[8];
                float acc0 = fmaf(ga.w, dC, baseC);
                float acc1 = fmaf(gb.w, dC, baseC);
                #pragma unroll
                for (int q = 0; q < 8; q++) {
                    float4 av = ra[q], bv = rb[q];
                    acc0 = fmaf(av.x, wreg[4 * q + 0], acc0);
                    acc1 = fmaf(bv.x, wreg[4 * q + 0], acc1);
                    acc0 = fmaf(av.y, wreg[4 * q + 1], acc0);
                    acc1 = fmaf(bv.y, wreg[4 * q + 1], acc1);
                    acc0 = fmaf(av.z, wreg[4 * q + 2], acc0);
                    acc1 = fmaf(bv.z, wreg[4 * q + 2], acc1);
                    acc0 = fmaf(av.w, wreg[4 * q + 3], acc0);
                    acc1 = fmaf(bv.w, wreg[4 * q + 3], acc1);
                }
                // interleaved sum / sumsq butterflies for both edges
                float s0 = acc0, q0 = acc0 * acc0;
                float s1 = acc1, q1 = acc1 * acc1;
                #pragma unroll
                for (int o = 16; o; o >>= 1) {
                    s0 += __shfl_xor_sync(0xffffffffu, s0, o);
                    q0 += __shfl_xor_sync(0xffffffffu, q0, o);
                    s1 += __shfl_xor_sync(0xffffffffu, s1, o);
                    q1 += __shfl_xor_sync(0xffffffffu, q1, o);
                }
                float mean0 = s0 * (1.0f / 32.0f);
                float mean1 = s1 * (1.0f / 32.0f);
                float var0 = q0 * (1.0f / 32.0f) - mean0 * mean0;
                float var1 = q1 * (1.0f / 32.0f) - mean1 * mean1;
                float iv0 = rsqrtf(var0 + 1e-5f);
                float iv1 = rsqrtf(var1 + 1e-5f);
                float so0 = (acc0 - mean0) * iv0 * lg + lb;
                float so1 = (acc1 - mean1) * iv1 * lg + lb;

                size_t eo = eo_base + (size_t)t * 128;
                out[eo + l]      = ga.x * whv;
                out[eo + 32 + l] = ga.y * whv;
                out[eo + 64 + l] = ga.z * whv;
                out[eo + 96 + l] = so0;
                eo += 128;
                out[eo + l]      = gb.x * whv;
                out[eo + 32 + l] = gb.y * whv;
                out[eo + 64 + l] = gb.z * whv;
                out[eo + 96 + l] = so1;
            }
            __syncwarp();
        }
    } else {
        // ========================= NODE PATH ===============================
        float* wsw  = (float*)smraw;          // 70*64
        float* whs  = wsw + 4480;             // 3*64
        float* whvs = whs + 192;              // 3*64
        float* wsb  = whvs + 192;             // 64
        float* glng = wsb + 64;               // 64
        float* glnb = glng + 64;              // 64
        float* sdi  = glnb + 64;              // 64*6
        float* vmat = sdi + 384;              // 64*9
        float* vnbuf = vmat + 576;            // 8*64 (16B aligned)

        int bt = bx - EDGE_BLOCKS;

        for (int idx = tid; idx < 4480; idx += 256) wsw[idx] = n_wsw[idx];
        for (int idx = tid; idx < 192; idx += 256)  whs[idx] = n_wh[idx];
        if (tid < 64) { wsb[tid] = n_wsb[tid]; glng[tid] = lnng[tid]; glnb[tid] = lnnb[tid]; }

        const float* Xbt = X + (size_t)bt * 768;
        if (tid < 192) {
            // dihedrals: one (i,t) per thread
            int i = tid / 3, t = tid - 3 * i;
            int r = 3 * i + t - 1;
            float ang = 0.0f;
            if (r >= 0 && r < 189) {
                float P[4][3];
                #pragma unroll
                for (int qq = 0; qq < 4; qq++) {
                    int p = r + qq;
                    const float* A = Xbt + (p / 3) * 12 + (p % 3) * 3;
                    P[qq][0] = A[0]; P[qq][1] = A[1]; P[qq][2] = A[2];
                }
                float u2x = P[1][0] - P[0][0], u2y = P[1][1] - P[0][1], u2z = P[1][2] - P[0][2];
                float u1x = P[2][0] - P[1][0], u1y = P[2][1] - P[1][1], u1z = P[2][2] - P[1][2];
                float u0x = P[3][0] - P[2][0], u0y = P[3][1] - P[2][1], u0z = P[3][2] - P[2][2];
                nrm3(u2x, u2y, u2z); nrm3(u1x, u1y, u1z); nrm3(u0x, u0y, u0z);
                float ax = u2y * u1z - u2z * u1y;
                float ay = u2z * u1x - u2x * u1z;
                float az = u2x * u1y - u2y * u1x; nrm3(ax, ay, az);
                float bx_ = u1y * u0z - u1z * u0y;
                float by_ = u1z * u0x - u1x * u0z;
                float bz_ = u1x * u0y - u1y * u0x; nrm3(bx_, by_, bz_);
                float cd = ax * bx_ + ay * by_ + az * bz_;
                cd = fminf(fmaxf(cd, -1.0f + 1e-7f), 1.0f - 1e-7f);
                float sg = u2x * bx_ + u2y * by_ + u2z * bz_;
                float sn = (sg > 0.f) ? 1.f : ((sg < 0.f) ? -1.f : 0.f);
                ang = sn * acosf(cd);
            }
            sdi[i * 6 + t]     = cosf(ang);
            sdi[i * 6 + 3 + t] = sinf(ang);
        } else {
            // frames: sidechain vec + fwd + bwd, one node per thread
            int i = tid - 192;
            const float* Xr = Xbt + (size_t)i * 12;
            float nx = Xr[0], ny = Xr[1], nz = Xr[2];
            float ox = Xr[3], oy = Xr[4], oz = Xr[5];
            float cx = Xr[6], cy = Xr[7], cz = Xr[8];
            float ccx = cx - ox, ccy = cy - oy, ccz = cz - oz; nrm3(ccx, ccy, ccz);
            float nnx = nx - ox, nny = ny - oy, nnz = nz - oz; nrm3(nnx, nny, nnz);
            float bxv = ccx + nnx, byv = ccy + nny, bzv = ccz + nnz; nrm3(bxv, byv, bzv);
            float px = ccy * nnz - ccz * nny;
            float py = ccz * nnx - ccx * nnz;
            float pz = ccx * nny - ccy * nnx; nrm3(px, py, pz);
            const float k1 = 0.57735026918962576f, k2 = 0.81649658092772603f;
            vmat[i * 9 + 0] = -bxv * k1 - px * k2;
            vmat[i * 9 + 3] = -byv * k1 - py * k2;
            vmat[i * 9 + 6] = -bzv * k1 - pz * k2;
            float fx = 0.f, fy = 0.f, fz = 0.f;
            if (i < 63) {
                const float* Xn2 = Xbt + (size_t)(i + 1) * 12 + 3;
                fx = Xn2[0] - ox; fy = Xn2[1] - oy; fz = Xn2[2] - oz; nrm3(fx, fy, fz);
            }
            vmat[i * 9 + 1] = fx; vmat[i * 9 + 4] = fy; vmat[i * 9 + 7] = fz;
            float gx = 0.f, gy = 0.f, gz = 0.f;
            if (i > 0) {
                const float* Xp = Xbt + (size_t)(i - 1) * 12 + 3;
                gx = ox - Xp[0]; gy = oy - Xp[1]; gz = oz - Xp[2]; nrm3(gx, gy, gz);
                gx = -gx; gy = -gy; gz = -gz;
            }
            vmat[i * 9 + 2] = gx; vmat[i * 9 + 5] = gy; vmat[i * 9 + 8] = gz;
        }
        __syncthreads();

        // whv = wh @ wv (3 x 64)
        for (int idx = tid; idx < 192; idx += 256) {
            int p = idx >> 6, h = idx & 63;
            float a = 0.f;
            for (int m = 0; m < 64; m++) a = fmaf(whs[p * 64 + m], n_wv[m * 64 + h], a);
            whvs[idx] = a;
        }
        __syncthreads();

        for (int nd = w; nd < 64; nd += 8) {
            float vm[9];
            #pragma unroll
            for (int z = 0; z < 9; z++) vm[z] = vmat[nd * 9 + z];
            int h0 = l, h1 = l + 32;
            float vh0[3], vh1[3];
            #pragma unroll
            for (int c = 0; c < 3; c++) {
                vh0[c] = vm[c * 3 + 0] * whs[0 * 64 + h0] + vm[c * 3 + 1] * whs[1 * 64 + h0] + vm[c * 3 + 2] * whs[2 * 64 + h0];
                vh1[c] = vm[c * 3 + 0] * whs[0 * 64 + h1] + vm[c * 3 + 1] * whs[1 * 64 + h1] + vm[c * 3 + 2] * whs[2 * 64 + h1];
            }
            float vn0 = sqrtf(vh0[0] * vh0[0] + vh0[1] * vh0[1] + vh0[2] * vh0[2] + 1e-8f);
            float vn1 = sqrtf(vh1[0] * vh1[0] + vh1[1] * vh1[1] + vh1[2] * vh1[2] + 1e-8f);
            vnbuf[w * 64 + l] = vn0;
            vnbuf[w * 64 + l + 32] = vn1;
            __syncwarp();

            float acc0 = wsb[h0], acc1 = wsb[h1];
            #pragma unroll
            for (int k = 0; k < 6; k++) {
                float dk = sdi[nd * 6 + k];
                acc0 = fmaf(dk, wsw[k * 64 + h0], acc0);
                acc1 = fmaf(dk, wsw[k * 64 + h1], acc1);
            }
            #pragma unroll
            for (int m = 0; m < 64; m += 4) {
                float4 v4 = *reinterpret_cast<const float4*>(&vnbuf[w * 64 + m]);
                acc0 = fmaf(v4.x, wsw[(6 + m) * 64 + h0], acc0);
                acc1 = fmaf(v4.x, wsw[(6 + m) * 64 + h1], acc1);
                acc0 = fmaf(v4.y, wsw[(7 + m) * 64 + h0], acc0);
                acc1 = fmaf(v4.y, wsw[(7 + m) * 64 + h1], acc1);
                acc0 = fmaf(v4.z, wsw[(8 + m) * 64 + h0], acc0);
                acc1 = fmaf(v4.z, wsw[(8 + m) * 64 + h1], acc1);
                acc0 = fmaf(v4.w, wsw[(9 + m) * 64 + h0], acc0);
                acc1 = fmaf(v4.w, wsw[(9 + m) * 64 + h1], acc1);
            }
            __syncwarp();

            float ssum = acc0 + acc1;
            #pragma unroll
            for (int o = 16; o; o >>= 1) ssum += __shfl_xor_sync(0xffffffffu, ssum, o);
            float mean = ssum * (1.0f / 64.0f);
            float dv0 = acc0 - mean, dv1 = acc1 - mean;
            float vs = dv0 * dv0 + dv1 * dv1;
            #pragma unroll
            for (int o = 16; o; o >>= 1) vs += __shfl_xor_sync(0xffffffffu, vs, o);
            float inv = 1.0f / sqrtf(vs * (1.0f / 64.0f) + 1e-5f);
            float o0 = dv0 * inv * glng[h0] + glnb[h0];
            float o1 = dv1 * inv * glng[h1] + glnb[h1];

            size_t vb = ((size_t)bt * 64 + nd) * 256;
            #pragma unroll
            for (int c = 0; c < 3; c++) {
                float vo0 = vm[c * 3 + 0] * whvs[0 * 64 + h0] + vm[c * 3 + 1] * whvs[1 * 64 + h0] + vm[c * 3 + 2] * whvs[2 * 64 + h0];
                float vo1 = vm[c * 3 + 0] * whvs[0 * 64 + h1] + vm[c * 3 + 1] * whvs[1 * 64 + h1] + vm[c * 3 + 2] * whvs[2 * 64 + h1];
                out[vb + c * 64 + h0] = vo0;
                out[vb + c * 64 + h1] = vo1;
            }
            out[vb + 192 + h0] = o0;
            out[vb + 192 + h1] = o1;
        }
    }
}

// ---------------------------------------------------------------------------
extern "C" void kernel_launch(void* const* d_in, const int* in_sizes, int n_in,
                              void* d_out, int out_size)
{
    const float* X      = (const float*)d_in[0];
    const float* mask   = (const float*)d_in[1];
    const int*   chain  = (const int*)d_in[2];
    const int*   focus  = (const int*)d_in[3];
    const float* n_wh   = (const float*)d_in[4];
    const float* n_wsw  = (const float*)d_in[5];
    const float* n_wsb  = (const float*)d_in[6];
    const float* n_wv   = (const float*)d_in[7];
    const float* e_wh   = (const float*)d_in[8];
    const float* e_wsw  = (const float*)d_in[9];
    const float* e_wsb  = (const float*)d_in[10];
    const float* e_wv   = (const float*)d_in[11];
    const float* ln_n_g = (const float*)d_in[12];
    const float* ln_n_b = (const float*)d_in[13];
    const float* ln_e_g = (const float*)d_in[14];
    const float* ln_e_b = (const float*)d_in[15];
    float* out = (float*)d_out;
    int L = in_sizes[2] / 2;

    init_postab_kernel<<<36, 256>>>();
    mega_kernel<<<EDGE_BLOCKS + NODE_BLOCKS, 256>>>(
        X, mask, chain, focus, L,
        n_wh, n_wsw, n_wsb, n_wv,
        e_wh, e_wsw, e_wsb, e_wv,
        ln_n_g, ln_n_b, ln_e_g, ln_e_b, out);
}

// round 5
// speedup vs baseline: 2.3060x; 1.2241x over previous
#include <cuda_runtime.h>
#include <math.h>

// Problem constants
#define BT  128                             // B*T
#define NEDGE (BT * 64 * 64)                // 524288
#define V_SZ  ((size_t)BT * 64 * 256)       // 2097152
#define E_SZ  ((size_t)NEDGE * 128)         // 67108864
#define OFF_E  (V_SZ)
#define OFF_EI (OFF_E + E_SZ)               // 69206016
#define OFF_AB (OFF_EI + (size_t)NEDGE)     // 69730304

#define EDGE_BLOCKS 1024                    // BT * 8
#define NODE_BLOCKS 128                     // BT

// epc[d][h] = sum_k Epos_k(d) * e_wsw[16+k][h],  d = an - i + 63 in [0,575)
__device__ float g_epc[575 * 32];

// ---------------------------------------------------------------------------
__global__ void init_epc_kernel(const float* __restrict__ e_wsw) {
    int idx = blockIdx.x * blockDim.x + threadIdx.x;
    if (idx >= 575 * 32) return;
    int dpos = idx >> 5;
    int h = idx & 31;
    float d = (float)(dpos - 63);
    float acc = 0.0f;
    #pragma unroll
    for (int j = 0; j < 8; j++) {
        float fr = expf((float)(2 * j) * (float)(-0.5756462732485114)); // -ln(1e4)/16
        float ang = d * fr;
        acc = fmaf(cosf(ang), e_wsw[(16 + j) * 32 + h], acc);
        acc = fmaf(sinf(ang), e_wsw[(24 + j) * 32 + h], acc);
    }
    g_epc[idx] = acc;
}

__device__ __forceinline__ void nrm3(float& x, float& y, float& z) {
    float n = sqrtf(x * x + y * y + z * z);
    float inv = 1.0f / fmaxf(n, 1e-12f);
    x *= inv; y *= inv; z *= inv;
}

// ---------------------------------------------------------------------------
// Mega kernel: blocks [0,1024) = fused sort+edge path, [1024,1152) = node path
// ---------------------------------------------------------------------------
__global__ __launch_bounds__(256) void mega_kernel(
    const float* __restrict__ X, const float* __restrict__ mask,
    const int* __restrict__ chain, const int* __restrict__ focus, int L,
    const float* __restrict__ n_wh,  const float* __restrict__ n_wsw,
    const float* __restrict__ n_wsb, const float* __restrict__ n_wv,
    const float* __restrict__ e_wh,  const float* __restrict__ e_wsw,
    const float* __restrict__ e_wsb, const float* __restrict__ e_wv,
    const float* __restrict__ lnng,  const float* __restrict__ lnnb,
    const float* __restrict__ lneg,  const float* __restrict__ lneb,
    float* __restrict__ out)
{
    __shared__ __align__(16) char smraw[32768];
    int bx = blockIdx.x;
    int tid = threadIdx.x, w = tid >> 5, l = tid & 31;

    if (bx < EDGE_BLOCKS) {
        // ================= EDGE PATH (fused sort + features + GVP + LN) ====
        float* feat = (float*)smraw;              // 8*32*24 = 6144 (16B aligned)
        float* xca  = feat + 6144;                // 192
        float* msk  = xca + 192;                  // 64
        int*   foc  = (int*)(msk + 64);           // 64
        int*   chs  = foc + 64;                   // 512
        float* Drow = (float*)(chs + 512);        // 8*64
        int*   erow = (int*)(Drow + 512);         // 8*64

        int bt = bx >> 3, rg = bx & 7, b = bt >> 6;
        const float* Xbt = X + (size_t)bt * 768;
        for (int idx = tid; idx < 192; idx += 256)
            xca[idx] = Xbt[(idx / 3) * 12 + 3 + (idx % 3)];
        if (tid < 64) {
            msk[tid] = mask[bt * 64 + tid];
            foc[tid] = focus[bt * 64 + tid];
        }
        const int* chainB = chain + b * L;
        bool chsm = (L <= 512);
        if (chsm) for (int idx = tid; idx < L; idx += 256) chs[idx] = chainB[idx];
        __syncthreads();

        // per-lane RBF weight column (rows 0..15 of ws_w) + folded constants
        float wreg[16];
        #pragma unroll
        for (int k = 0; k < 16; k++) wreg[k] = e_wsw[k * 32 + l];
        float vnc = 0.f, selfc = 0.f, whv = 0.f;
        #pragma unroll
        for (int m = 0; m < 32; m++) {
            float whm = e_wh[m];
            float wsv = e_wsw[(32 + m) * 32 + l];
            vnc   = fmaf(sqrtf(fmaf(whm, whm, 1e-8f)), wsv, vnc);  // |dir|=1
            selfc = fmaf(sqrtf(1e-8f), wsv, selfc);                // dir==0
            whv   = fmaf(whm, e_wv[m * 32 + l], whv);
        }
        float bias = e_wsb[l];
        float baseC = bias + vnc;
        float dC = selfc - vnc;                 // selfC - baseC
        float lg = lneg[l], lb = lneb[l];

        // ---- per-warp row: distances + stable argsort (rank count) ----
        int i = rg * 8 + w;
        float xix = xca[i * 3], xiy = xca[i * 3 + 1], xiz = xca[i * 3 + 2];
        float mi = msk[i];

        int j0 = l, j1 = l + 32;
        float d0, d1, a0, a1;
        {
            float dx = __fadd_rn(xca[j0 * 3],     -xix);
            float dy = __fadd_rn(xca[j0 * 3 + 1], -xiy);
            float dz = __fadd_rn(xca[j0 * 3 + 2], -xiz);
            float s = __fadd_rn(__fadd_rn(__fmul_rn(dx, dx), __fmul_rn(dy, dy)), __fmul_rn(dz, dz));
            d0 = __fmul_rn(__fmul_rn(msk[j0], mi), sqrtf(__fadd_rn(s, 1e-6f)));
            dx = __fadd_rn(xca[j1 * 3],     -xix);
            dy = __fadd_rn(xca[j1 * 3 + 1], -xiy);
            dz = __fadd_rn(xca[j1 * 3 + 2], -xiz);
            s = __fadd_rn(__fadd_rn(__fmul_rn(dx, dx), __fmul_rn(dy, dy)), __fmul_rn(dz, dz));
            d1 = __fmul_rn(__fmul_rn(msk[j1], mi), sqrtf(__fadd_rn(s, 1e-6f)));
        }
        float mx = fmaxf(d0, d1);
        #pragma unroll
        for (int o = 16; o; o >>= 1) mx = fmaxf(mx, __shfl_xor_sync(0xffffffffu, mx, o));
        float dmax = mx + 1.0f;
        {
            float m20 = __fmul_rn(msk[j0], mi);
            float m21 = __fmul_rn(msk[j1], mi);
            a0 = __fadd_rn(d0, __fmul_rn(1.0f - m20, dmax));
            a1 = __fadd_rn(d1, __fmul_rn(1.0f - m21, dmax));
        }
        Drow[w * 64 + j0] = a0;
        Drow[w * 64 + j1] = a1;
        __syncwarp();
        int r0 = 0, r1 = 0;
        #pragma unroll 16
        for (int k = 0; k < 64; k++) {
            float dk = Drow[w * 64 + k];
            r0 += (int)(dk < a0) | ((int)(dk == a0) & (int)(k < j0));
            r1 += (int)(dk < a1) | ((int)(dk == a1) & (int)(k < j1));
        }
        erow[w * 64 + r0] = j0;
        erow[w * 64 + r1] = j1;
        __syncwarp();

        int nbr0 = erow[w * 64];
        int c0 = chsm ? chs[foc[nbr0]] : chainB[foc[nbr0]];
        size_t gebase = (size_t)bt * 4096 + (size_t)i * 64;
        float4* frl = (float4*)(feat + w * 768 + l * 24);
        const float4* fw = (const float4*)(feat + w * 768);

        for (int t2 = 0; t2 < 2; t2++) {
            // ---- phase 1: lane = edge, build 24-float feature row ----
            int e = t2 * 32 + l;
            int nbr = erow[w * 64 + e];
            float dn = Drow[w * 64 + nbr];
            int an = foc[nbr];
            size_t ge = gebase + e;
            out[OFF_EI + ge] = (float)nbr;
            out[OFF_AB + ge] = (float)an;

            float dx = xca[nbr * 3]     - xix;
            float dy = xca[nbr * 3 + 1] - xiy;
            float dz = xca[nbr * 3 + 2] - xiz;
            float n2 = dx * dx + dy * dy + dz * dz;
            float invn = 1.0f / fmaxf(sqrtf(n2), 1e-12f);

            // RBF (16 values, 4 float4s)
            #pragma unroll
            for (int q = 0; q < 4; q++) {
                float4 v;
                float t0 = (dn - (float)(4 * q + 0) * (20.0f / 15.0f)) * 0.8f;
                float t1 = (dn - (float)(4 * q + 1) * (20.0f / 15.0f)) * 0.8f;
                float tA = (dn - (float)(4 * q + 2) * (20.0f / 15.0f)) * 0.8f;
                float tB = (dn - (float)(4 * q + 3) * (20.0f / 15.0f)) * 0.8f;
                v.x = __expf(-t0 * t0); v.y = __expf(-t1 * t1);
                v.z = __expf(-tA * tA); v.w = __expf(-tB * tB);
                frl[q] = v;
            }
            {
                float4 v = {dx * invn, dy * invn, dz * invn, (n2 == 0.0f) ? 1.0f : 0.0f};
                frl[4] = v;
            }
            {
                float sf = ((chsm ? chs[an] : chainB[an]) == c0) ? 1.0f : 0.0f;
                float4 v = {sf, (float)(an - i + 63), 0.0f, 0.0f};
                frl[5] = v;
            }
            __syncwarp();

            // ---- phase 2: lane = channel, 2-edge interleaved GVP + LN ----
            size_t eo_base = OFF_E + (gebase + (size_t)(t2 * 32)) * 128;
            for (int t = 0; t < 32; t += 2) {
                const float4* ra = fw + t * 6;
                const float4* rb = ra + 6;
                float4 ga = ra[4], gb = rb[4];
                float4 xa = ra[5], xb = rb[5];
                int da = (int)xa.y, db = (int)xb.y;
                float ea = g_epc[da * 32 + l];
                float eb = g_epc[db * 32 + l];
                float acc0 = fmaf(ga.w, dC, baseC);
                float acc1 = fmaf(gb.w, dC, baseC);
                acc0 = fmaf(xa.x, ea, acc0);
                acc1 = fmaf(xb.x, eb, acc1);
                #pragma unroll
                for (int q = 0; q < 4; q++) {
                    float4 av = ra[q], bv = rb[q];
                    acc0 = fmaf(av.x, wreg[4 * q + 0], acc0);
                    acc1 = fmaf(bv.x, wreg[4 * q + 0], acc1);
                    acc0 = fmaf(av.y, wreg[4 * q + 1], acc0);
                    acc1 = fmaf(bv.y, wreg[4 * q + 1], acc1);
                    acc0 = fmaf(av.z, wreg[4 * q + 2], acc0);
                    acc1 = fmaf(bv.z, wreg[4 * q + 2], acc1);
                    acc0 = fmaf(av.w, wreg[4 * q + 3], acc0);
                    acc1 = fmaf(bv.w, wreg[4 * q + 3], acc1);
                }
                // 4-way interleaved butterflies (sum / sumsq for both edges)
                float s0 = acc0, q0 = acc0 * acc0;
                float s1 = acc1, q1 = acc1 * acc1;
                #pragma unroll
                for (int o = 16; o; o >>= 1) {
                    s0 += __shfl_xor_sync(0xffffffffu, s0, o);
                    q0 += __shfl_xor_sync(0xffffffffu, q0, o);
                    s1 += __shfl_xor_sync(0xffffffffu, s1, o);
                    q1 += __shfl_xor_sync(0xffffffffu, q1, o);
                }
                float mean0 = s0 * (1.0f / 32.0f);
                float mean1 = s1 * (1.0f / 32.0f);
                float var0 = fmaf(q0, 1.0f / 32.0f, -mean0 * mean0);
                float var1 = fmaf(q1, 1.0f / 32.0f, -mean1 * mean1);
                float iv0 = rsqrtf(var0 + 1e-5f);
                float iv1 = rsqrtf(var1 + 1e-5f);
                float so0 = (acc0 - mean0) * iv0 * lg + lb;
                float so1 = (acc1 - mean1) * iv1 * lg + lb;

                size_t eo = eo_base + (size_t)t * 128;
                out[eo + l]      = ga.x * whv;
                out[eo + 32 + l] = ga.y * whv;
                out[eo + 64 + l] = ga.z * whv;
                out[eo + 96 + l] = so0;
                eo += 128;
                out[eo + l]      = gb.x * whv;
                out[eo + 32 + l] = gb.y * whv;
                out[eo + 64 + l] = gb.z * whv;
                out[eo + 96 + l] = so1;
            }
            __syncwarp();
        }
    } else {
        // ========================= NODE PATH ===============================
        float* wsw  = (float*)smraw;          // 70*64
        float* whs  = wsw + 4480;             // 3*64
        float* whvs = whs + 192;              // 3*64
        float* wsb  = whvs + 192;             // 64
        float* glng = wsb + 64;               // 64
        float* glnb = glng + 64;              // 64
        float* sdi  = glnb + 64;              // 64*6
        float* vmat = sdi + 384;              // 64*9
        float* vnbuf = vmat + 576;            // 8*64 (16B aligned)

        int bt = bx - EDGE_BLOCKS;

        for (int idx = tid; idx < 4480; idx += 256) wsw[idx] = n_wsw[idx];
        for (int idx = tid; idx < 192; idx += 256)  whs[idx] = n_wh[idx];
        if (tid < 64) { wsb[tid] = n_wsb[tid]; glng[tid] = lnng[tid]; glnb[tid] = lnnb[tid]; }

        const float* Xbt = X + (size_t)bt * 768;
        if (tid < 192) {
            // dihedrals: one (i,t) per thread
            int i = tid / 3, t = tid - 3 * i;
            int r = 3 * i + t - 1;
            float ang = 0.0f;
            if (r >= 0 && r < 189) {
                float P[4][3];
                #pragma unroll
                for (int qq = 0; qq < 4; qq++) {
                    int p = r + qq;
                    const float* A = Xbt + (p / 3) * 12 + (p % 3) * 3;
                    P[qq][0] = A[0]; P[qq][1] = A[1]; P[qq][2] = A[2];
                }
                float u2x = P[1][0] - P[0][0], u2y = P[1][1] - P[0][1], u2z = P[1][2] - P[0][2];
                float u1x = P[2][0] - P[1][0], u1y = P[2][1] - P[1][1], u1z = P[2][2] - P[1][2];
                float u0x = P[3][0] - P[2][0], u0y = P[3][1] - P[2][1], u0z = P[3][2] - P[2][2];
                nrm3(u2x, u2y, u2z); nrm3(u1x, u1y, u1z); nrm3(u0x, u0y, u0z);
                float ax = u2y * u1z - u2z * u1y;
                float ay = u2z * u1x - u2x * u1z;
                float az = u2x * u1y - u2y * u1x; nrm3(ax, ay, az);
                float bx_ = u1y * u0z - u1z * u0y;
                float by_ = u1z * u0x - u1x * u0z;
                float bz_ = u1x * u0y - u1y * u0x; nrm3(bx_, by_, bz_);
                float cd = ax * bx_ + ay * by_ + az * bz_;
                cd = fminf(fmaxf(cd, -1.0f + 1e-7f), 1.0f - 1e-7f);
                float sg = u2x * bx_ + u2y * by_ + u2z * bz_;
                float sn = (sg > 0.f) ? 1.f : ((sg < 0.f) ? -1.f : 0.f);
                ang = sn * acosf(cd);
            }
            sdi[i * 6 + t]     = cosf(ang);
            sdi[i * 6 + 3 + t] = sinf(ang);
        } else {
            // frames: sidechain vec + fwd + bwd, one node per thread
            int i = tid - 192;
            const float* Xr = Xbt + (size_t)i * 12;
            float nx = Xr[0], ny = Xr[1], nz = Xr[2];
            float ox = Xr[3], oy = Xr[4], oz = Xr[5];
            float cx = Xr[6], cy = Xr[7], cz = Xr[8];
            float ccx = cx - ox, ccy = cy - oy, ccz = cz - oz; nrm3(ccx, ccy, ccz);
            float nnx = nx - ox, nny = ny - oy, nnz = nz - oz; nrm3(nnx, nny, nnz);
            float bxv = ccx + nnx, byv = ccy + nny, bzv = ccz + nnz; nrm3(bxv, byv, bzv);
            float px = ccy * nnz - ccz * nny;
            float py = ccz * nnx - ccx * nnz;
            float pz = ccx * nny - ccy * nnx; nrm3(px, py, pz);
            const float k1 = 0.57735026918962576f, k2 = 0.81649658092772603f;
            vmat[i * 9 + 0] = -bxv * k1 - px * k2;
            vmat[i * 9 + 3] = -byv * k1 - py * k2;
            vmat[i * 9 + 6] = -bzv * k1 - pz * k2;
            float fx = 0.f, fy = 0.f, fz = 0.f;
            if (i < 63) {
                const float* Xn2 = Xbt + (size_t)(i + 1) * 12 + 3;
                fx = Xn2[0] - ox; fy = Xn2[1] - oy; fz = Xn2[2] - oz; nrm3(fx, fy, fz);
            }
            vmat[i * 9 + 1] = fx; vmat[i * 9 + 4] = fy; vmat[i * 9 + 7] = fz;
            float gx = 0.f, gy = 0.f, gz = 0.f;
            if (i > 0) {
                const float* Xp = Xbt + (size_t)(i - 1) * 12 + 3;
                gx = ox - Xp[0]; gy = oy - Xp[1]; gz = oz - Xp[2]; nrm3(gx, gy, gz);
                gx = -gx; gy = -gy; gz = -gz;
            }
            vmat[i * 9 + 2] = gx; vmat[i * 9 + 5] = gy; vmat[i * 9 + 8] = gz;
        }
        __syncthreads();

        // whv = wh @ wv (3 x 64)
        for (int idx = tid; idx < 192; idx += 256) {
            int p = idx >> 6, h = idx & 63;
            float a = 0.f;
            for (int m = 0; m < 64; m++) a = fmaf(whs[p * 64 + m], n_wv[m * 64 + h], a);
            whvs[idx] = a;
        }
        __syncthreads();

        for (int nd = w; nd < 64; nd += 8) {
            float vm[9];
            #pragma unroll
            for (int z = 0; z < 9; z++) vm[z] = vmat[nd * 9 + z];
            int h0 = l, h1 = l + 32;
            float vh0[3], vh1[3];
            #pragma unroll
            for (int c = 0; c < 3; c++) {
                vh0[c] = vm[c * 3 + 0] * whs[0 * 64 + h0] + vm[c * 3 + 1] * whs[1 * 64 + h0] + vm[c * 3 + 2] * whs[2 * 64 + h0];
                vh1[c] = vm[c * 3 + 0] * whs[0 * 64 + h1] + vm[c * 3 + 1] * whs[1 * 64 + h1] + vm[c * 3 + 2] * whs[2 * 64 + h1];
            }
            float vn0 = sqrtf(vh0[0] * vh0[0] + vh0[1] * vh0[1] + vh0[2] * vh0[2] + 1e-8f);
            float vn1 = sqrtf(vh1[0] * vh1[0] + vh1[1] * vh1[1] + vh1[2] * vh1[2] + 1e-8f);
            vnbuf[w * 64 + l] = vn0;
            vnbuf[w * 64 + l + 32] = vn1;
            __syncwarp();

            float acc0 = wsb[h0], acc1 = wsb[h1];
            #pragma unroll
            for (int k = 0; k < 6; k++) {
                float dk = sdi[nd * 6 + k];
                acc0 = fmaf(dk, wsw[k * 64 + h0], acc0);
                acc1 = fmaf(dk, wsw[k * 64 + h1], acc1);
            }
            #pragma unroll
            for (int m = 0; m < 64; m += 4) {
                float4 v4 = *reinterpret_cast<const float4*>(&vnbuf[w * 64 + m]);
                acc0 = fmaf(v4.x, wsw[(6 + m) * 64 + h0], acc0);
                acc1 = fmaf(v4.x, wsw[(6 + m) * 64 + h1], acc1);
                acc0 = fmaf(v4.y, wsw[(7 + m) * 64 + h0], acc0);
                acc1 = fmaf(v4.y, wsw[(7 + m) * 64 + h1], acc1);
                acc0 = fmaf(v4.z, wsw[(8 + m) * 64 + h0], acc0);
                acc1 = fmaf(v4.z, wsw[(8 + m) * 64 + h1], acc1);
                acc0 = fmaf(v4.w, wsw[(9 + m) * 64 + h0], acc0);
                acc1 = fmaf(v4.w, wsw[(9 + m) * 64 + h1], acc1);
            }
            __syncwarp();

            // LayerNorm over 64 channels: 2 interleaved butterflies
            float ssum = acc0 + acc1;
            #pragma unroll
            for (int o = 16; o; o >>= 1) ssum += __shfl_xor_sync(0xffffffffu, ssum, o);
            float mean = ssum * (1.0f / 64.0f);
            float dv0 = acc0 - mean, dv1 = acc1 - mean;
            float vs = dv0 * dv0 + dv1 * dv1;
            #pragma unroll
            for (int o = 16; o; o >>= 1) vs += __shfl_xor_sync(0xffffffffu, vs, o);
            float inv = rsqrtf(vs * (1.0f / 64.0f) + 1e-5f);
            float o0 = dv0 * inv * glng[h0] + glnb[h0];
            float o1 = dv1 * inv * glng[h1] + glnb[h1];

            size_t vb = ((size_t)bt * 64 + nd) * 256;
            #pragma unroll
            for (int c = 0; c < 3; c++) {
                float vo0 = vm[c * 3 + 0] * whvs[0 * 64 + h0] + vm[c * 3 + 1] * whvs[1 * 64 + h0] + vm[c * 3 + 2] * whvs[2 * 64 + h0];
                float vo1 = vm[c * 3 + 0] * whvs[0 * 64 + h1] + vm[c * 3 + 1] * whvs[1 * 64 + h1] + vm[c * 3 + 2] * whvs[2 * 64 + h1];
                out[vb + c * 64 + h0] = vo0;
                out[vb + c * 64 + h1] = vo1;
            }
            out[vb + 192 + h0] = o0;
            out[vb + 192 + h1] = o1;
        }
    }
}

// ---------------------------------------------------------------------------
extern "C" void kernel_launch(void* const* d_in, const int* in_sizes, int n_in,
                              void* d_out, int out_size)
{
    const float* X      = (const float*)d_in[0];
    const float* mask   = (const float*)d_in[1];
    const int*   chain  = (const int*)d_in[2];
    const int*   focus  = (const int*)d_in[3];
    const float* n_wh   = (const float*)d_in[4];
    const float* n_wsw  = (const float*)d_in[5];
    const float* n_wsb  = (const float*)d_in[6];
    const float* n_wv   = (const float*)d_in[7];
    const float* e_wh   = (const float*)d_in[8];
    const float* e_wsw  = (const float*)d_in[9];
    const float* e_wsb  = (const float*)d_in[10];
    const float* e_wv   = (const float*)d_in[11];
    const float* ln_n_g = (const float*)d_in[12];
    const float* ln_n_b = (const float*)d_in[13];
    const float* ln_e_g = (const float*)d_in[14];
    const float* ln_e_b = (const float*)d_in[15];
    float* out = (float*)d_out;
    int L = in_sizes[2] / 2;

    init_epc_kernel<<<72, 256>>>(e_wsw);
    mega_kernel<<<EDGE_BLOCKS + NODE_BLOCKS, 256>>>(
        X, mask, chain, focus, L,
        n_wh, n_wsw, n_wsb, n_wv,
        e_wh, e_wsw, e_wsb, e_wv,
        ln_n_g, ln_n_b, ln_e_g, ln_e_b, out);
}

// round 6
// speedup vs baseline: 2.5363x; 1.0998x over previous
#include <cuda_runtime.h>
#include <math.h>

// Problem constants
#define BT  128                             // B*T
#define NEDGE (BT * 64 * 64)                // 524288
#define V_SZ  ((size_t)BT * 64 * 256)       // 2097152
#define E_SZ  ((size_t)NEDGE * 128)         // 67108864
#define OFF_E  (V_SZ)
#define OFF_EI (OFF_E + E_SZ)               // 69206016
#define OFF_AB (OFF_EI + (size_t)NEDGE)     // 69730304

#define EDGE_BLOCKS 1024                    // BT * 8
#define NODE_BLOCKS 128                     // BT

// Precomputed per-channel edge constants (all mean-centered over h so the
// LayerNorm mean folds away):
__device__ float g_wc[16 * 32];     // centered RBF weight rows 0..15
__device__ float g_base[32];        // centered (bias + vn-fold), |dir|=1 case
__device__ float g_dC[32];          // centered (self-case minus base-case)
__device__ float g_whv[32];         // wh @ wv  (v_out projection)
__device__ float g_epcc[575 * 32];  // centered  sum_k Epos_k(d) * W[16+k][h]

__device__ __forceinline__ float bfly_sum(float v) {
    #pragma unroll
    for (int o = 16; o; o >>= 1) v += __shfl_xor_sync(0xffffffffu, v, o);
    return v;
}

// ---------------------------------------------------------------------------
__global__ void init_params_kernel(
    const float* __restrict__ e_wh, const float* __restrict__ e_wsw,
    const float* __restrict__ e_wsb, const float* __restrict__ e_wv)
{
    int l = threadIdx.x;                    // one warp
    float vnc = 0.f, selfc = 0.f, whv = 0.f;
    for (int m = 0; m < 32; m++) {
        float whm = e_wh[m];
        float wsv = e_wsw[(32 + m) * 32 + l];
        vnc   = fmaf(sqrtf(fmaf(whm, whm, 1e-8f)), wsv, vnc);
        selfc = fmaf(sqrtf(1e-8f), wsv, selfc);
        whv   = fmaf(whm, e_wv[m * 32 + l], whv);
    }
    float base = e_wsb[l] + vnc;
    float dC = selfc - vnc;
    g_base[l] = base - bfly_sum(base) * (1.0f / 32.0f);
    g_dC[l]   = dC   - bfly_sum(dC)   * (1.0f / 32.0f);
    g_whv[l]  = whv;
    for (int k = 0; k < 16; k++) {
        float wk = e_wsw[k * 32 + l];
        g_wc[k * 32 + l] = wk - bfly_sum(wk) * (1.0f / 32.0f);
    }
}

// epcc[d][h], centered per d-row.  d = an - i + 63 in [0,575)
__global__ void init_epcc_kernel(const float* __restrict__ e_wsw) {
    int g = blockIdx.x * 8 + (threadIdx.x >> 5);
    int l = threadIdx.x & 31;
    if (g >= 575) return;
    float d = (float)(g - 63);
    float acc = 0.0f;
    #pragma unroll
    for (int j = 0; j < 8; j++) {
        float fr = expf((float)(2 * j) * (float)(-0.5756462732485114)); // -ln(1e4)/16
        float ang = d * fr;
        acc = fmaf(cosf(ang), e_wsw[(16 + j) * 32 + l], acc);
        acc = fmaf(sinf(ang), e_wsw[(24 + j) * 32 + l], acc);
    }
    g_epcc[g * 32 + l] = acc - bfly_sum(acc) * (1.0f / 32.0f);
}

__device__ __forceinline__ void nrm3(float& x, float& y, float& z) {
    float n = sqrtf(x * x + y * y + z * z);
    float inv = 1.0f / fmaxf(n, 1e-12f);
    x *= inv; y *= inv; z *= inv;
}

// ---------------------------------------------------------------------------
// Mega kernel: blocks [0,1024) = fused sort+edge path, [1024,1152) = node path
// ---------------------------------------------------------------------------
__global__ __launch_bounds__(256) void mega_kernel(
    const float* __restrict__ X, const float* __restrict__ mask,
    const int* __restrict__ chain, const int* __restrict__ focus, int L,
    const float* __restrict__ n_wh,  const float* __restrict__ n_wsw,
    const float* __restrict__ n_wsb, const float* __restrict__ n_wv,
    const float* __restrict__ lnng,  const float* __restrict__ lnnb,
    const float* __restrict__ lneg,  const float* __restrict__ lneb,
    float* __restrict__ out)
{
    __shared__ __align__(16) char smraw[28416];
    int bx = blockIdx.x;
    int tid = threadIdx.x, w = tid >> 5, l = tid & 31;

    if (bx < EDGE_BLOCKS) {
        // ================= EDGE PATH (fused sort + features + GVP + LN) ====
        float* feat = (float*)smraw;              // 8*32*20 = 5120 (16B aligned)
        float* xca  = feat + 5120;                // 192
        float* msk  = xca + 192;                  // 64
        int*   foc  = (int*)(msk + 64);           // 64
        int*   chs  = foc + 64;                   // 512
        float* Drow = (float*)(chs + 512);        // 8*64
        int*   erow = (int*)(Drow + 512);         // 8*64

        int bt = bx >> 3, rg = bx & 7, b = bt >> 6;
        const float* Xbt = X + (size_t)bt * 768;
        for (int idx = tid; idx < 192; idx += 256)
            xca[idx] = Xbt[(idx / 3) * 12 + 3 + (idx % 3)];
        if (tid < 64) {
            msk[tid] = mask[bt * 64 + tid];
            foc[tid] = focus[bt * 64 + tid];
        }
        const int* chainB = chain + b * L;
        bool chsm = (L <= 512);
        if (chsm) for (int idx = tid; idx < L; idx += 256) chs[idx] = chainB[idx];
        __syncthreads();

        // per-lane centered weights / constants
        float wreg[16];
        #pragma unroll
        for (int k = 0; k < 16; k++) wreg[k] = g_wc[k * 32 + l];
        float baseC = g_base[l];
        float dCc   = g_dC[l];
        float whv   = g_whv[l];
        float lg = lneg[l], lb = lneb[l];

        // ---- per-warp row: distances + stable argsort (rank count) ----
        int i = rg * 8 + w;
        float xix = xca[i * 3], xiy = xca[i * 3 + 1], xiz = xca[i * 3 + 2];
        float mi = msk[i];

        int j0 = l, j1 = l + 32;
        float d0, d1, a0, a1;
        {
            float dx = __fadd_rn(xca[j0 * 3],     -xix);
            float dy = __fadd_rn(xca[j0 * 3 + 1], -xiy);
            float dz = __fadd_rn(xca[j0 * 3 + 2], -xiz);
            float s = __fadd_rn(__fadd_rn(__fmul_rn(dx, dx), __fmul_rn(dy, dy)), __fmul_rn(dz, dz));
            d0 = __fmul_rn(__fmul_rn(msk[j0], mi), sqrtf(__fadd_rn(s, 1e-6f)));
            dx = __fadd_rn(xca[j1 * 3],     -xix);
            dy = __fadd_rn(xca[j1 * 3 + 1], -xiy);
            dz = __fadd_rn(xca[j1 * 3 + 2], -xiz);
            s = __fadd_rn(__fadd_rn(__fmul_rn(dx, dx), __fmul_rn(dy, dy)), __fmul_rn(dz, dz));
            d1 = __fmul_rn(__fmul_rn(msk[j1], mi), sqrtf(__fadd_rn(s, 1e-6f)));
        }
        float mx = fmaxf(d0, d1);
        #pragma unroll
        for (int o = 16; o; o >>= 1) mx = fmaxf(mx, __shfl_xor_sync(0xffffffffu, mx, o));
        float dmax = mx + 1.0f;
        {
            float m20 = __fmul_rn(msk[j0], mi);
            float m21 = __fmul_rn(msk[j1], mi);
            a0 = __fadd_rn(d0, __fmul_rn(1.0f - m20, dmax));
            a1 = __fadd_rn(d1, __fmul_rn(1.0f - m21, dmax));
        }
        Drow[w * 64 + j0] = a0;
        Drow[w * 64 + j1] = a1;
        __syncwarp();
        int r0 = 0, r1 = 0;
        #pragma unroll 16
        for (int k = 0; k < 64; k++) {
            float dk = Drow[w * 64 + k];
            r0 += (int)(dk < a0) | ((int)(dk == a0) & (int)(k < j0));
            r1 += (int)(dk < a1) | ((int)(dk == a1) & (int)(k < j1));
        }
        erow[w * 64 + r0] = j0;
        erow[w * 64 + r1] = j1;
        __syncwarp();

        int nbr0 = erow[w * 64];
        int c0 = chsm ? chs[foc[nbr0]] : chainB[foc[nbr0]];
        size_t gebase = (size_t)bt * 4096 + (size_t)i * 64;
        float4* frl = (float4*)(feat + w * 640 + l * 20);
        const float* fw = feat + w * 640;

        for (int t2 = 0; t2 < 2; t2++) {
            // ---- phase 1: lane = edge, build 20-float feature row ----
            int e = t2 * 32 + l;
            int nbr = erow[w * 64 + e];
            float dn = Drow[w * 64 + nbr];
            int an = foc[nbr];
            size_t ge = gebase + e;
            out[OFF_EI + ge] = (float)nbr;
            out[OFF_AB + ge] = (float)an;

            float dx = xca[nbr * 3]     - xix;
            float dy = xca[nbr * 3 + 1] - xiy;
            float dz = xca[nbr * 3 + 2] - xiz;
            float n2 = dx * dx + dy * dy + dz * dz;
            float invn = 1.0f / fmaxf(sqrtf(n2), 1e-12f);

            // RBF (16 values, 4 float4s)
            #pragma unroll
            for (int q = 0; q < 4; q++) {
                float4 v;
                float t0 = (dn - (float)(4 * q + 0) * (20.0f / 15.0f)) * 0.8f;
                float t1 = (dn - (float)(4 * q + 1) * (20.0f / 15.0f)) * 0.8f;
                float tA = (dn - (float)(4 * q + 2) * (20.0f / 15.0f)) * 0.8f;
                float tB = (dn - (float)(4 * q + 3) * (20.0f / 15.0f)) * 0.8f;
                v.x = __expf(-t0 * t0); v.y = __expf(-t1 * t1);
                v.z = __expf(-tA * tA); v.w = __expf(-tB * tB);
                frl[q] = v;
            }
            {
                int same  = ((chsm ? chs[an] : chainB[an]) == c0) ? 1 : 0;
                int selff = (n2 == 0.0f) ? 1 : 0;
                int code = (an - i + 63) | (same << 10) | (selff << 11);
                float4 v = {dx * invn, dy * invn, dz * invn, (float)code};
                frl[4] = v;
            }
            __syncwarp();

            // ---- phase 2: lane = channel, 2-edge interleaved, LN-centered ----
            size_t eo_base = OFF_E + (gebase + (size_t)(t2 * 32)) * 128;
            for (int t = 0; t < 32; t += 2) {
                const float4* ra = (const float4*)(fw + t * 20);
                const float4* rb = (const float4*)(fw + t * 20 + 20);
                float4 ga = ra[4], gb = rb[4];
                int ca = (int)ga.w, cb = (int)gb.w;
                float ea = g_epcc[(ca & 1023) * 32 + l];
                float eb = g_epcc[(cb & 1023) * 32 + l];
                float sfa = (float)((ca >> 10) & 1), sfb = (float)((cb >> 10) & 1);
                float sla = (float)(ca >> 11),       slb = (float)(cb >> 11);
                // dv = s_out - mean  (all terms pre-centered over channels)
                float dv0 = fmaf(sla, dCc, baseC);
                float dv1 = fmaf(slb, dCc, baseC);
                dv0 = fmaf(sfa, ea, dv0);
                dv1 = fmaf(sfb, eb, dv1);
                #pragma unroll
                for (int q = 0; q < 4; q++) {
                    float4 av = ra[q], bv = rb[q];
                    dv0 = fmaf(av.x, wreg[4 * q + 0], dv0);
                    dv1 = fmaf(bv.x, wreg[4 * q + 0], dv1);
                    dv0 = fmaf(av.y, wreg[4 * q + 1], dv0);
                    dv1 = fmaf(bv.y, wreg[4 * q + 1], dv1);
                    dv0 = fmaf(av.z, wreg[4 * q + 2], dv0);
                    dv1 = fmaf(bv.z, wreg[4 * q + 2], dv1);
                    dv0 = fmaf(av.w, wreg[4 * q + 3], dv0);
                    dv1 = fmaf(bv.w, wreg[4 * q + 3], dv1);
                }
                // single variance butterfly per edge (2-way interleaved)
                float q0 = dv0 * dv0, q1 = dv1 * dv1;
                #pragma unroll
                for (int o = 16; o; o >>= 1) {
                    q0 += __shfl_xor_sync(0xffffffffu, q0, o);
                    q1 += __shfl_xor_sync(0xffffffffu, q1, o);
                }
                float iv0 = rsqrtf(fmaf(q0, 1.0f / 32.0f, 1e-5f));
                float iv1 = rsqrtf(fmaf(q1, 1.0f / 32.0f, 1e-5f));
                float so0 = fmaf(dv0 * iv0, lg, lb);
                float so1 = fmaf(dv1 * iv1, lg, lb);

                size_t eo = eo_base + (size_t)t * 128;
                out[eo + l]      = ga.x * whv;
                out[eo + 32 + l] = ga.y * whv;
                out[eo + 64 + l] = ga.z * whv;
                out[eo + 96 + l] = so0;
                eo += 128;
                out[eo + l]      = gb.x * whv;
                out[eo + 32 + l] = gb.y * whv;
                out[eo + 64 + l] = gb.z * whv;
                out[eo + 96 + l] = so1;
            }
            __syncwarp();
        }
    } else {
        // ========================= NODE PATH ===============================
        float* wsw  = (float*)smraw;          // 70*64
        float* whs  = wsw + 4480;             // 3*64
        float* whvs = whs + 192;              // 3*64
        float* wsb  = whvs + 192;             // 64
        float* glng = wsb + 64;               // 64
        float* glnb = glng + 64;              // 64
        float* sdi  = glnb + 64;              // 64*6
        float* vmat = sdi + 384;              // 64*9
        float* vnbuf = vmat + 576;            // 8*64 (16B aligned)

        int bt = bx - EDGE_BLOCKS;

        for (int idx = tid; idx < 4480; idx += 256) wsw[idx] = n_wsw[idx];
        for (int idx = tid; idx < 192; idx += 256)  whs[idx] = n_wh[idx];
        if (tid < 64) { wsb[tid] = n_wsb[tid]; glng[tid] = lnng[tid]; glnb[tid] = lnnb[tid]; }

        const float* Xbt = X + (size_t)bt * 768;
        if (tid < 192) {
            // dihedrals: one (i,t) per thread
            int i = tid / 3, t = tid - 3 * i;
            int r = 3 * i + t - 1;
            float ang = 0.0f;
            if (r >= 0 && r < 189) {
                float P[4][3];
                #pragma unroll
                for (int qq = 0; qq < 4; qq++) {
                    int p = r + qq;
                    const float* A = Xbt + (p / 3) * 12 + (p % 3) * 3;
                    P[qq][0] = A[0]; P[qq][1] = A[1]; P[qq][2] = A[2];
                }
                float u2x = P[1][0] - P[0][0], u2y = P[1][1] - P[0][1], u2z = P[1][2] - P[0][2];
                float u1x = P[2][0] - P[1][0], u1y = P[2][1] - P[1][1], u1z = P[2][2] - P[1][2];
                float u0x = P[3][0] - P[2][0], u0y = P[3][1] - P[2][1], u0z = P[3][2] - P[2][2];
                nrm3(u2x, u2y, u2z); nrm3(u1x, u1y, u1z); nrm3(u0x, u0y, u0z);
                float ax = u2y * u1z - u2z * u1y;
                float ay = u2z * u1x - u2x * u1z;
                float az = u2x * u1y - u2y * u1x; nrm3(ax, ay, az);
                float bx_ = u1y * u0z - u1z * u0y;
                float by_ = u1z * u0x - u1x * u0z;
                float bz_ = u1x * u0y - u1y * u0x; nrm3(bx_, by_, bz_);
                float cd = ax * bx_ + ay * by_ + az * bz_;
                cd = fminf(fmaxf(cd, -1.0f + 1e-7f), 1.0f - 1e-7f);
                float sg = u2x * bx_ + u2y * by_ + u2z * bz_;
                float sn = (sg > 0.f) ? 1.f : ((sg < 0.f) ? -1.f : 0.f);
                ang = sn * acosf(cd);
            }
            sdi[i * 6 + t]     = cosf(ang);
            sdi[i * 6 + 3 + t] = sinf(ang);
        } else {
            // frames: sidechain vec + fwd + bwd, one node per thread
            int i = tid - 192;
            const float* Xr = Xbt + (size_t)i * 12;
            float nx = Xr[0], ny = Xr[1], nz = Xr[2];
            float ox = Xr[3], oy = Xr[4], oz = Xr[5];
            float cx = Xr[6], cy = Xr[7], cz = Xr[8];
            float ccx = cx - ox, ccy = cy - oy, ccz = cz - oz; nrm3(ccx, ccy, ccz);
            float nnx = nx - ox, nny = ny - oy, nnz = nz - oz; nrm3(nnx, nny, nnz);
            float bxv = ccx + nnx, byv = ccy + nny, bzv = ccz + nnz; nrm3(bxv, byv, bzv);
            float px = ccy * nnz - ccz * nny;
            float py = ccz * nnx - ccx * nnz;
            float pz = ccx * nny - ccy * nnx; nrm3(px, py, pz);
            const float k1 = 0.57735026918962576f, k2 = 0.81649658092772603f;
            vmat[i * 9 + 0] = -bxv * k1 - px * k2;
            vmat[i * 9 + 3] = -byv * k1 - py * k2;
            vmat[i * 9 + 6] = -bzv * k1 - pz * k2;
            float fx = 0.f, fy = 0.f, fz = 0.f;
            if (i < 63) {
                const float* Xn2 = Xbt + (size_t)(i + 1) * 12 + 3;
                fx = Xn2[0] - ox; fy = Xn2[1] - oy; fz = Xn2[2] - oz; nrm3(fx, fy, fz);
            }
            vmat[i * 9 + 1] = fx; vmat[i * 9 + 4] = fy; vmat[i * 9 + 7] = fz;
            float gx = 0.f, gy = 0.f, gz = 0.f;
            if (i > 0) {
                const float* Xp = Xbt + (size_t)(i - 1) * 12 + 3;
                gx = ox - Xp[0]; gy = oy - Xp[1]; gz = oz - Xp[2]; nrm3(gx, gy, gz);
                gx = -gx; gy = -gy; gz = -gz;
            }
            vmat[i * 9 + 2] = gx; vmat[i * 9 + 5] = gy; vmat[i * 9 + 8] = gz;
        }
        __syncthreads();

        // whv = wh @ wv (3 x 64)
        for (int idx = tid; idx < 192; idx += 256) {
            int p = idx >> 6, h = idx & 63;
            float a = 0.f;
            for (int m = 0; m < 64; m++) a = fmaf(whs[p * 64 + m], n_wv[m * 64 + h], a);
            whvs[idx] = a;
        }
        __syncthreads();

        for (int nd = w; nd < 64; nd += 8) {
            float vm[9];
            #pragma unroll
            for (int z = 0; z < 9; z++) vm[z] = vmat[nd * 9 + z];
            int h0 = l, h1 = l + 32;
            float vh0[3], vh1[3];
            #pragma unroll
            for (int c = 0; c < 3; c++) {
                vh0[c] = vm[c * 3 + 0] * whs[0 * 64 + h0] + vm[c * 3 + 1] * whs[1 * 64 + h0] + vm[c * 3 + 2] * whs[2 * 64 + h0];
                vh1[c] = vm[c * 3 + 0] * whs[0 * 64 + h1] + vm[c * 3 + 1] * whs[1 * 64 + h1] + vm[c * 3 + 2] * whs[2 * 64 + h1];
            }
            float vn0 = sqrtf(vh0[0] * vh0[0] + vh0[1] * vh0[1] + vh0[2] * vh0[2] + 1e-8f);
            float vn1 = sqrtf(vh1[0] * vh1[0] + vh1[1] * vh1[1] + vh1[2] * vh1[2] + 1e-8f);
            vnbuf[w * 64 + l] = vn0;
            vnbuf[w * 64 + l + 32] = vn1;
            __syncwarp();

            float acc0 = wsb[h0], acc1 = wsb[h1];
            #pragma unroll
            for (int k = 0; k < 6; k++) {
                float dk = sdi[nd * 6 + k];
                acc0 = fmaf(dk, wsw[k * 64 + h0], acc0);
                acc1 = fmaf(dk, wsw[k * 64 + h1], acc1);
            }
            #pragma unroll
            for (int m = 0; m < 64; m += 4) {
                float4 v4 = *reinterpret_cast<const float4*>(&vnbuf[w * 64 + m]);
                acc0 = fmaf(v4.x, wsw[(6 + m) * 64 + h0], acc0);
                acc1 = fmaf(v4.x, wsw[(6 + m) * 64 + h1], acc1);
                acc0 = fmaf(v4.y, wsw[(7 + m) * 64 + h0], acc0);
                acc1 = fmaf(v4.y, wsw[(7 + m) * 64 + h1], acc1);
                acc0 = fmaf(v4.z, wsw[(8 + m) * 64 + h0], acc0);
                acc1 = fmaf(v4.z, wsw[(8 + m) * 64 + h1], acc1);
                acc0 = fmaf(v4.w, wsw[(9 + m) * 64 + h0], acc0);
                acc1 = fmaf(v4.w, wsw[(9 + m) * 64 + h1], acc1);
            }
            __syncwarp();

            // LayerNorm over 64 channels: 2 interleaved butterflies
            float ssum = acc0 + acc1;
            #pragma unroll
            for (int o = 16; o; o >>= 1) ssum += __shfl_xor_sync(0xffffffffu, ssum, o);
            float mean = ssum * (1.0f / 64.0f);
            float dv0 = acc0 - mean, dv1 = acc1 - mean;
            float vs = dv0 * dv0 + dv1 * dv1;
            #pragma unroll
            for (int o = 16; o; o >>= 1) vs += __shfl_xor_sync(0xffffffffu, vs, o);
            float inv = rsqrtf(vs * (1.0f / 64.0f) + 1e-5f);
            float o0 = dv0 * inv * glng[h0] + glnb[h0];
            float o1 = dv1 * inv * glng[h1] + glnb[h1];

            size_t vb = ((size_t)bt * 64 + nd) * 256;
            #pragma unroll
            for (int c = 0; c < 3; c++) {
                float vo0 = vm[c * 3 + 0] * whvs[0 * 64 + h0] + vm[c * 3 + 1] * whvs[1 * 64 + h0] + vm[c * 3 + 2] * whvs[2 * 64 + h0];
                float vo1 = vm[c * 3 + 0] * whvs[0 * 64 + h1] + vm[c * 3 + 1] * whvs[1 * 64 + h1] + vm[c * 3 + 2] * whvs[2 * 64 + h1];
                out[vb + c * 64 + h0] = vo0;
                out[vb + c * 64 + h1] = vo1;
            }
            out[vb + 192 + h0] = o0;
            out[vb + 192 + h1] = o1;
        }
    }
}

// ---------------------------------------------------------------------------
extern "C" void kernel_launch(void* const* d_in, const int* in_sizes, int n_in,
                              void* d_out, int out_size)
{
    const float* X      = (const float*)d_in[0];
    const float* mask   = (const float*)d_in[1];
    const int*   chain  = (const int*)d_in[2];
    const int*   focus  = (const int*)d_in[3];
    const float* n_wh   = (const float*)d_in[4];
    const float* n_wsw  = (const float*)d_in[5];
    const float* n_wsb  = (const float*)d_in[6];
    const float* n_wv   = (const float*)d_in[7];
    const float* e_wh   = (const float*)d_in[8];
    const float* e_wsw  = (const float*)d_in[9];
    const float* e_wsb  = (const float*)d_in[10];
    const float* e_wv   = (const float*)d_in[11];
    const float* ln_n_g = (const float*)d_in[12];
    const float* ln_n_b = (const float*)d_in[13];
    const float* ln_e_g = (const float*)d_in[14];
    const float* ln_e_b = (const float*)d_in[15];
    float* out = (float*)d_out;
    int L = in_sizes[2] / 2;

    init_params_kernel<<<1, 32>>>(e_wh, e_wsw, e_wsb, e_wv);
    init_epcc_kernel<<<72, 256>>>(e_wsw);
    mega_kernel<<<EDGE_BLOCKS + NODE_BLOCKS, 256>>>(
        X, mask, chain, focus, L,
        n_wh, n_wsw, n_wsb, n_wv,
        ln_n_g, ln_n_b, ln_e_g, ln_e_b, out);
}

// round 7
// speedup vs baseline: 3.0086x; 1.1862x over previous
#include <cuda_runtime.h>
#include <math.h>

// Problem constants
#define BT  128                             // B*T
#define NEDGE (BT * 64 * 64)                // 524288
#define V_SZ  ((size_t)BT * 64 * 256)       // 2097152
#define E_SZ  ((size_t)NEDGE * 128)         // 67108864
#define OFF_E  (V_SZ)
#define OFF_EI (OFF_E + E_SZ)               // 69206016
#define OFF_AB (OFF_EI + (size_t)NEDGE)     // 69730304

#define EDGE_BLOCKS 1024                    // BT * 8
#define NODE_BLOCKS 128                     // BT

// Precomputed per-channel edge constants (all mean-centered over h so the
// LayerNorm mean folds away):
__device__ float g_wc[16 * 32];     // centered RBF weight rows 0..15
__device__ float g_base[32];        // centered (bias + vn-fold), |dir|=1 case
__device__ float g_dC[32];          // centered (self-case minus base-case)
__device__ float g_whv[32];         // wh @ wv  (v_out projection)
__device__ float g_epcc[575 * 32];  // centered  sum_k Epos_k(d) * W[16+k][h]

__device__ __forceinline__ float bfly_sum(float v) {
    #pragma unroll
    for (int o = 16; o; o >>= 1) v += __shfl_xor_sync(0xffffffffu, v, o);
    return v;
}

// ---------------------------------------------------------------------------
// Parallel init: 32 warps.  warp = output channel h, lane = inner index m.
// Each warp reduces its 32-term folds via butterfly (1 LDG round, MLP=32).
// Warps 0..15 additionally center the 16 RBF weight rows (k=warp, h=lane).
// ---------------------------------------------------------------------------
__global__ __launch_bounds__(1024) void init_params_kernel(
    const float* __restrict__ e_wh, const float* __restrict__ e_wsw,
    const float* __restrict__ e_wsb, const float* __restrict__ e_wv)
{
    __shared__ float sbase[32], sdC[32];
    int w = threadIdx.x >> 5, l = threadIdx.x & 31;

    // centered RBF rows (k = w, h = l): mean over h = butterfly over lanes
    if (w < 16) {
        float wk = e_wsw[w * 32 + l];
        g_wc[w * 32 + l] = wk - bfly_sum(wk) * (1.0f / 32.0f);
    }

    // per-channel folds: h = w, m = l
    {
        float whm = e_wh[l];
        float wsv = e_wsw[(32 + l) * 32 + w];
        float wv  = e_wv[l * 32 + w];
        float vnc   = bfly_sum(sqrtf(fmaf(whm, whm, 1e-8f)) * wsv);
        float selfc = bfly_sum(sqrtf(1e-8f) * wsv);
        float whv   = bfly_sum(whm * wv);
        if (l == 0) {
            sbase[w] = e_wsb[w] + vnc;
            sdC[w]   = selfc - vnc;
            g_whv[w] = whv;
        }
    }
    __syncthreads();
    if (w == 0) {
        float b = sbase[l];
        g_base[l] = b - bfly_sum(b) * (1.0f / 32.0f);
        float d = sdC[l];
        g_dC[l]   = d - bfly_sum(d) * (1.0f / 32.0f);
    }
}

// epcc[d][h], centered per d-row.  d = an - i + 63 in [0,575)
__global__ void init_epcc_kernel(const float* __restrict__ e_wsw) {
    int g = blockIdx.x * 8 + (threadIdx.x >> 5);
    int l = threadIdx.x & 31;
    if (g >= 575) return;
    float d = (float)(g - 63);
    float acc = 0.0f;
    #pragma unroll
    for (int j = 0; j < 8; j++) {
        float fr = expf((float)(2 * j) * (float)(-0.5756462732485114)); // -ln(1e4)/16
        float ang = d * fr;
        acc = fmaf(cosf(ang), e_wsw[(16 + j) * 32 + l], acc);
        acc = fmaf(sinf(ang), e_wsw[(24 + j) * 32 + l], acc);
    }
    g_epcc[g * 32 + l] = acc - bfly_sum(acc) * (1.0f / 32.0f);
}

__device__ __forceinline__ void nrm3(float& x, float& y, float& z) {
    float n = sqrtf(x * x + y * y + z * z);
    float inv = 1.0f / fmaxf(n, 1e-12f);
    x *= inv; y *= inv; z *= inv;
}

// ---------------------------------------------------------------------------
// Mega kernel: blocks [0,1024) = fused sort+edge path, [1024,1152) = node path
// ---------------------------------------------------------------------------
__global__ __launch_bounds__(256) void mega_kernel(
    const float* __restrict__ X, const float* __restrict__ mask,
    const int* __restrict__ chain, const int* __restrict__ focus, int L,
    const float* __restrict__ n_wh,  const float* __restrict__ n_wsw,
    const float* __restrict__ n_wsb, const float* __restrict__ n_wv,
    const float* __restrict__ lnng,  const float* __restrict__ lnnb,
    const float* __restrict__ lneg,  const float* __restrict__ lneb,
    float* __restrict__ out)
{
    __shared__ __align__(16) char smraw[28416];
    int bx = blockIdx.x;
    int tid = threadIdx.x, w = tid >> 5, l = tid & 31;

    if (bx < EDGE_BLOCKS) {
        // ================= EDGE PATH (fused sort + features + GVP + LN) ====
        float* feat = (float*)smraw;              // 8*32*20 = 5120 (16B aligned)
        float* xca  = feat + 5120;                // 192
        float* msk  = xca + 192;                  // 64
        int*   foc  = (int*)(msk + 64);           // 64
        int*   chs  = foc + 64;                   // 512
        float* Drow = (float*)(chs + 512);        // 8*64
        int*   erow = (int*)(Drow + 512);         // 8*64

        int bt = bx >> 3, rg = bx & 7, b = bt >> 6;
        const float* Xbt = X + (size_t)bt * 768;
        for (int idx = tid; idx < 192; idx += 256)
            xca[idx] = Xbt[(idx / 3) * 12 + 3 + (idx % 3)];
        if (tid < 64) {
            msk[tid] = mask[bt * 64 + tid];
            foc[tid] = focus[bt * 64 + tid];
        }
        const int* chainB = chain + b * L;
        bool chsm = (L <= 512);
        if (chsm) for (int idx = tid; idx < L; idx += 256) chs[idx] = chainB[idx];
        __syncthreads();

        // per-lane centered weights / constants
        float wreg[16];
        #pragma unroll
        for (int k = 0; k < 16; k++) wreg[k] = g_wc[k * 32 + l];
        float baseC = g_base[l];
        float dCc   = g_dC[l];
        float whv   = g_whv[l];
        float lg = lneg[l], lb = lneb[l];

        // ---- per-warp row: distances + stable argsort (rank count) ----
        int i = rg * 8 + w;
        float xix = xca[i * 3], xiy = xca[i * 3 + 1], xiz = xca[i * 3 + 2];
        float mi = msk[i];

        int j0 = l, j1 = l + 32;
        float d0, d1, a0, a1;
        {
            float dx = __fadd_rn(xca[j0 * 3],     -xix);
            float dy = __fadd_rn(xca[j0 * 3 + 1], -xiy);
            float dz = __fadd_rn(xca[j0 * 3 + 2], -xiz);
            float s = __fadd_rn(__fadd_rn(__fmul_rn(dx, dx), __fmul_rn(dy, dy)), __fmul_rn(dz, dz));
            d0 = __fmul_rn(__fmul_rn(msk[j0], mi), sqrtf(__fadd_rn(s, 1e-6f)));
            dx = __fadd_rn(xca[j1 * 3],     -xix);
            dy = __fadd_rn(xca[j1 * 3 + 1], -xiy);
            dz = __fadd_rn(xca[j1 * 3 + 2], -xiz);
            s = __fadd_rn(__fadd_rn(__fmul_rn(dx, dx), __fmul_rn(dy, dy)), __fmul_rn(dz, dz));
            d1 = __fmul_rn(__fmul_rn(msk[j1], mi), sqrtf(__fadd_rn(s, 1e-6f)));
        }
        float mx = fmaxf(d0, d1);
        #pragma unroll
        for (int o = 16; o; o >>= 1) mx = fmaxf(mx, __shfl_xor_sync(0xffffffffu, mx, o));
        float dmax = mx + 1.0f;
        {
            float m20 = __fmul_rn(msk[j0], mi);
            float m21 = __fmul_rn(msk[j1], mi);
            a0 = __fadd_rn(d0, __fmul_rn(1.0f - m20, dmax));
            a1 = __fadd_rn(d1, __fmul_rn(1.0f - m21, dmax));
        }
        Drow[w * 64 + j0] = a0;
        Drow[w * 64 + j1] = a1;
        __syncwarp();
        int r0 = 0, r1 = 0;
        #pragma unroll 16
        for (int k = 0; k < 64; k++) {
            float dk = Drow[w * 64 + k];
            r0 += (int)(dk < a0) | ((int)(dk == a0) & (int)(k < j0));
            r1 += (int)(dk < a1) | ((int)(dk == a1) & (int)(k < j1));
        }
        erow[w * 64 + r0] = j0;
        erow[w * 64 + r1] = j1;
        __syncwarp();

        int nbr0 = erow[w * 64];
        int c0 = chsm ? chs[foc[nbr0]] : chainB[foc[nbr0]];
        size_t gebase = (size_t)bt * 4096 + (size_t)i * 64;
        float4* frl = (float4*)(feat + w * 640 + l * 20);
        const float* fw = feat + w * 640;

        for (int t2 = 0; t2 < 2; t2++) {
            // ---- phase 1: lane = edge, build 20-float feature row ----
            int e = t2 * 32 + l;
            int nbr = erow[w * 64 + e];
            float dn = Drow[w * 64 + nbr];
            int an = foc[nbr];
            size_t ge = gebase + e;
            out[OFF_EI + ge] = (float)nbr;
            out[OFF_AB + ge] = (float)an;

            float dx = xca[nbr * 3]     - xix;
            float dy = xca[nbr * 3 + 1] - xiy;
            float dz = xca[nbr * 3 + 2] - xiz;
            float n2 = dx * dx + dy * dy + dz * dz;
            float invn = 1.0f / fmaxf(sqrtf(n2), 1e-12f);

            // RBF (16 values, 4 float4s)
            #pragma unroll
            for (int q = 0; q < 4; q++) {
                float4 v;
                float t0 = (dn - (float)(4 * q + 0) * (20.0f / 15.0f)) * 0.8f;
                float t1 = (dn - (float)(4 * q + 1) * (20.0f / 15.0f)) * 0.8f;
                float tA = (dn - (float)(4 * q + 2) * (20.0f / 15.0f)) * 0.8f;
                float tB = (dn - (float)(4 * q + 3) * (20.0f / 15.0f)) * 0.8f;
                v.x = __expf(-t0 * t0); v.y = __expf(-t1 * t1);
                v.z = __expf(-tA * tA); v.w = __expf(-tB * tB);
                frl[q] = v;
            }
            {
                int same  = ((chsm ? chs[an] : chainB[an]) == c0) ? 1 : 0;
                int selff = (n2 == 0.0f) ? 1 : 0;
                int code = (an - i + 63) | (same << 10) | (selff << 11);
                float4 v = {dx * invn, dy * invn, dz * invn, (float)code};
                frl[4] = v;
            }
            __syncwarp();

            // ---- phase 2: lane = channel, 2-edge interleaved, LN-centered ----
            size_t eo_base = OFF_E + (gebase + (size_t)(t2 * 32)) * 128;
            for (int t = 0; t < 32; t += 2) {
                const float4* ra = (const float4*)(fw + t * 20);
                const float4* rb = (const float4*)(fw + t * 20 + 20);
                float4 ga = ra[4], gb = rb[4];
                int ca = (int)ga.w, cb = (int)gb.w;
                float ea = g_epcc[(ca & 1023) * 32 + l];
                float eb = g_epcc[(cb & 1023) * 32 + l];
                float sfa = (float)((ca >> 10) & 1), sfb = (float)((cb >> 10) & 1);
                float sla = (float)(ca >> 11),       slb = (float)(cb >> 11);
                // dv = s_out - mean  (all terms pre-centered over channels)
                float dv0 = fmaf(sla, dCc, baseC);
                float dv1 = fmaf(slb, dCc, baseC);
                dv0 = fmaf(sfa, ea, dv0);
                dv1 = fmaf(sfb, eb, dv1);
                #pragma unroll
                for (int q = 0; q < 4; q++) {
                    float4 av = ra[q], bv = rb[q];
                    dv0 = fmaf(av.x, wreg[4 * q + 0], dv0);
                    dv1 = fmaf(bv.x, wreg[4 * q + 0], dv1);
                    dv0 = fmaf(av.y, wreg[4 * q + 1], dv0);
                    dv1 = fmaf(bv.y, wreg[4 * q + 1], dv1);
                    dv0 = fmaf(av.z, wreg[4 * q + 2], dv0);
                    dv1 = fmaf(bv.z, wreg[4 * q + 2], dv1);
                    dv0 = fmaf(av.w, wreg[4 * q + 3], dv0);
                    dv1 = fmaf(bv.w, wreg[4 * q + 3], dv1);
                }
                // single variance butterfly per edge (2-way interleaved)
                float q0 = dv0 * dv0, q1 = dv1 * dv1;
                #pragma unroll
                for (int o = 16; o; o >>= 1) {
                    q0 += __shfl_xor_sync(0xffffffffu, q0, o);
                    q1 += __shfl_xor_sync(0xffffffffu, q1, o);
                }
                float iv0 = rsqrtf(fmaf(q0, 1.0f / 32.0f, 1e-5f));
                float iv1 = rsqrtf(fmaf(q1, 1.0f / 32.0f, 1e-5f));
                float so0 = fmaf(dv0 * iv0, lg, lb);
                float so1 = fmaf(dv1 * iv1, lg, lb);

                size_t eo = eo_base + (size_t)t * 128;
                out[eo + l]      = ga.x * whv;
                out[eo + 32 + l] = ga.y * whv;
                out[eo + 64 + l] = ga.z * whv;
                out[eo + 96 + l] = so0;
                eo += 128;
                out[eo + l]      = gb.x * whv;
                out[eo + 32 + l] = gb.y * whv;
                out[eo + 64 + l] = gb.z * whv;
                out[eo + 96 + l] = so1;
            }
            __syncwarp();
        }
    } else {
        // ========================= NODE PATH ===============================
        float* wsw  = (float*)smraw;          // 70*64
        float* whs  = wsw + 4480;             // 3*64
        float* whvs = whs + 192;              // 3*64
        float* wsb  = whvs + 192;             // 64
        float* glng = wsb + 64;               // 64
        float* glnb = glng + 64;              // 64
        float* sdi  = glnb + 64;              // 64*6
        float* vmat = sdi + 384;              // 64*9
        float* vnbuf = vmat + 576;            // 8*64 (16B aligned)

        int bt = bx - EDGE_BLOCKS;

        for (int idx = tid; idx < 4480; idx += 256) wsw[idx] = n_wsw[idx];
        for (int idx = tid; idx < 192; idx += 256)  whs[idx] = n_wh[idx];
        if (tid < 64) { wsb[tid] = n_wsb[tid]; glng[tid] = lnng[tid]; glnb[tid] = lnnb[tid]; }

        const float* Xbt = X + (size_t)bt * 768;
        if (tid < 192) {
            // dihedrals: one (i,t) per thread
            int i = tid / 3, t = tid - 3 * i;
            int r = 3 * i + t - 1;
            float ang = 0.0f;
            if (r >= 0 && r < 189) {
                float P[4][3];
                #pragma unroll
                for (int qq = 0; qq < 4; qq++) {
                    int p = r + qq;
                    const float* A = Xbt + (p / 3) * 12 + (p % 3) * 3;
                    P[qq][0] = A[0]; P[qq][1] = A[1]; P[qq][2] = A[2];
                }
                float u2x = P[1][0] - P[0][0], u2y = P[1][1] - P[0][1], u2z = P[1][2] - P[0][2];
                float u1x = P[2][0] - P[1][0], u1y = P[2][1] - P[1][1], u1z = P[2][2] - P[1][2];
                float u0x = P[3][0] - P[2][0], u0y = P[3][1] - P[2][1], u0z = P[3][2] - P[2][2];
                nrm3(u2x, u2y, u2z); nrm3(u1x, u1y, u1z); nrm3(u0x, u0y, u0z);
                float ax = u2y * u1z - u2z * u1y;
                float ay = u2z * u1x - u2x * u1z;
                float az = u2x * u1y - u2y * u1x; nrm3(ax, ay, az);
                float bx_ = u1y * u0z - u1z * u0y;
                float by_ = u1z * u0x - u1x * u0z;
                float bz_ = u1x * u0y - u1y * u0x; nrm3(bx_, by_, bz_);
                float cd = ax * bx_ + ay * by_ + az * bz_;
                cd = fminf(fmaxf(cd, -1.0f + 1e-7f), 1.0f - 1e-7f);
                float sg = u2x * bx_ + u2y * by_ + u2z * bz_;
                float sn = (sg > 0.f) ? 1.f : ((sg < 0.f) ? -1.f : 0.f);
                ang = sn * acosf(cd);
            }
            sdi[i * 6 + t]     = cosf(ang);
            sdi[i * 6 + 3 + t] = sinf(ang);
        } else {
            // frames: sidechain vec + fwd + bwd, one node per thread
            int i = tid - 192;
            const float* Xr = Xbt + (size_t)i * 12;
            float nx = Xr[0], ny = Xr[1], nz = Xr[2];
            float ox = Xr[3], oy = Xr[4], oz = Xr[5];
            float cx = Xr[6], cy = Xr[7], cz = Xr[8];
            float ccx = cx - ox, ccy = cy - oy, ccz = cz - oz; nrm3(ccx, ccy, ccz);
            float nnx = nx - ox, nny = ny - oy, nnz = nz - oz; nrm3(nnx, nny, nnz);
            float bxv = ccx + nnx, byv = ccy + nny, bzv = ccz + nnz; nrm3(bxv, byv, bzv);
            float px = ccy * nnz - ccz * nny;
            float py = ccz * nnx - ccx * nnz;
            float pz = ccx * nny - ccy * nnx; nrm3(px, py, pz);
            const float k1 = 0.57735026918962576f, k2 = 0.81649658092772603f;
            vmat[i * 9 + 0] = -bxv * k1 - px * k2;
            vmat[i * 9 + 3] = -byv * k1 - py * k2;
            vmat[i * 9 + 6] = -bzv * k1 - pz * k2;
            float fx = 0.f, fy = 0.f, fz = 0.f;
            if (i < 63) {
                const float* Xn2 = Xbt + (size_t)(i + 1) * 12 + 3;
                fx = Xn2[0] - ox; fy = Xn2[1] - oy; fz = Xn2[2] - oz; nrm3(fx, fy, fz);
            }
            vmat[i * 9 + 1] = fx; vmat[i * 9 + 4] = fy; vmat[i * 9 + 7] = fz;
            float gx = 0.f, gy = 0.f, gz = 0.f;
            if (i > 0) {
                const float* Xp = Xbt + (size_t)(i - 1) * 12 + 3;
                gx = ox - Xp[0]; gy = oy - Xp[1]; gz = oz - Xp[2]; nrm3(gx, gy, gz);
                gx = -gx; gy = -gy; gz = -gz;
            }
            vmat[i * 9 + 2] = gx; vmat[i * 9 + 5] = gy; vmat[i * 9 + 8] = gz;
        }
        __syncthreads();

        // whv = wh @ wv (3 x 64)
        for (int idx = tid; idx < 192; idx += 256) {
            int p = idx >> 6, h = idx & 63;
            float a = 0.f;
            for (int m = 0; m < 64; m++) a = fmaf(whs[p * 64 + m], n_wv[m * 64 + h], a);
            whvs[idx] = a;
        }
        __syncthreads();

        for (int nd = w; nd < 64; nd += 8) {
            float vm[9];
            #pragma unroll
            for (int z = 0; z < 9; z++) vm[z] = vmat[nd * 9 + z];
            int h0 = l, h1 = l + 32;
            float vh0[3], vh1[3];
            #pragma unroll
            for (int c = 0; c < 3; c++) {
                vh0[c] = vm[c * 3 + 0] * whs[0 * 64 + h0] + vm[c * 3 + 1] * whs[1 * 64 + h0] + vm[c * 3 + 2] * whs[2 * 64 + h0];
                vh1[c] = vm[c * 3 + 0] * whs[0 * 64 + h1] + vm[c * 3 + 1] * whs[1 * 64 + h1] + vm[c * 3 + 2] * whs[2 * 64 + h1];
            }
            float vn0 = sqrtf(vh0[0] * vh0[0] + vh0[1] * vh0[1] + vh0[2] * vh0[2] + 1e-8f);
            float vn1 = sqrtf(vh1[0] * vh1[0] + vh1[1] * vh1[1] + vh1[2] * vh1[2] + 1e-8f);
            vnbuf[w * 64 + l] = vn0;
            vnbuf[w * 64 + l + 32] = vn1;
            __syncwarp();

            float acc0 = wsb[h0], acc1 = wsb[h1];
            #pragma unroll
            for (int k = 0; k < 6; k++) {
                float dk = sdi[nd * 6 + k];
                acc0 = fmaf(dk, wsw[k * 64 + h0], acc0);
                acc1 = fmaf(dk, wsw[k * 64 + h1], acc1);
            }
            #pragma unroll
            for (int m = 0; m < 64; m += 4) {
                float4 v4 = *reinterpret_cast<const float4*>(&vnbuf[w * 64 + m]);
                acc0 = fmaf(v4.x, wsw[(6 + m) * 64 + h0], acc0);
                acc1 = fmaf(v4.x, wsw[(6 + m) * 64 + h1], acc1);
                acc0 = fmaf(v4.y, wsw[(7 + m) * 64 + h0], acc0);
                acc1 = fmaf(v4.y, wsw[(7 + m) * 64 + h1], acc1);
                acc0 = fmaf(v4.z, wsw[(8 + m) * 64 + h0], acc0);
                acc1 = fmaf(v4.z, wsw[(8 + m) * 64 + h1], acc1);
                acc0 = fmaf(v4.w, wsw[(9 + m) * 64 + h0], acc0);
                acc1 = fmaf(v4.w, wsw[(9 + m) * 64 + h1], acc1);
            }
            __syncwarp();

            // LayerNorm over 64 channels: 2 interleaved butterflies
            float ssum = acc0 + acc1;
            #pragma unroll
            for (int o = 16; o; o >>= 1) ssum += __shfl_xor_sync(0xffffffffu, ssum, o);
            float mean = ssum * (1.0f / 64.0f);
            float dv0 = acc0 - mean, dv1 = acc1 - mean;
            float vs = dv0 * dv0 + dv1 * dv1;
            #pragma unroll
            for (int o = 16; o; o >>= 1) vs += __shfl_xor_sync(0xffffffffu, vs, o);
            float inv = rsqrtf(vs * (1.0f / 64.0f) + 1e-5f);
            float o0 = dv0 * inv * glng[h0] + glnb[h0];
            float o1 = dv1 * inv * glng[h1] + glnb[h1];

            size_t vb = ((size_t)bt * 64 + nd) * 256;
            #pragma unroll
            for (int c = 0; c < 3; c++) {
                float vo0 = vm[c * 3 + 0] * whvs[0 * 64 + h0] + vm[c * 3 + 1] * whvs[1 * 64 + h0] + vm[c * 3 + 2] * whvs[2 * 64 + h0];
                float vo1 = vm[c * 3 + 0] * whvs[0 * 64 + h1] + vm[c * 3 + 1] * whvs[1 * 64 + h1] + vm[c * 3 + 2] * whvs[2 * 64 + h1];
                out[vb + c * 64 + h0] = vo0;
                out[vb + c * 64 + h1] = vo1;
            }
            out[vb + 192 + h0] = o0;
            out[vb + 192 + h1] = o1;
        }
    }
}

// ---------------------------------------------------------------------------
extern "C" void kernel_launch(void* const* d_in, const int* in_sizes, int n_in,
                              void* d_out, int out_size)
{
    const float* X      = (const float*)d_in[0];
    const float* mask   = (const float*)d_in[1];
    const int*   chain  = (const int*)d_in[2];
    const int*   focus  = (const int*)d_in[3];
    const float* n_wh   = (const float*)d_in[4];
    const float* n_wsw  = (const float*)d_in[5];
    const float* n_wsb  = (const float*)d_in[6];
    const float* n_wv   = (const float*)d_in[7];
    const float* e_wh   = (const float*)d_in[8];
    const float* e_wsw  = (const float*)d_in[9];
    const float* e_wsb  = (const float*)d_in[10];
    const float* e_wv   = (const float*)d_in[11];
    const float* ln_n_g = (const float*)d_in[12];
    const float* ln_n_b = (const float*)d_in[13];
    const float* ln_e_g = (const float*)d_in[14];
    const float* ln_e_b = (const float*)d_in[15];
    float* out = (float*)d_out;
    int L = in_sizes[2] / 2;

    init_epcc_kernel<<<72, 256>>>(e_wsw);
    init_params_kernel<<<1, 1024>>>(e_wh, e_wsw, e_wsb, e_wv);
    mega_kernel<<<EDGE_BLOCKS + NODE_BLOCKS, 256>>>(
        X, mask, chain, focus, L,
        n_wh, n_wsw, n_wsb, n_wv,
        ln_n_g, ln_n_b, ln_e_g, ln_e_b, out);
}

// round 8
// speedup vs baseline: 3.2312x; 1.0740x over previous
#include <cuda_runtime.h>
#include <math.h>

// Problem constants
#define BT  128                             // B*T
#define NEDGE (BT * 64 * 64)                // 524288
#define V_SZ  ((size_t)BT * 64 * 256)       // 2097152
#define E_SZ  ((size_t)NEDGE * 128)         // 67108864
#define OFF_E  (V_SZ)
#define OFF_EI (OFF_E + E_SZ)               // 69206016
#define OFF_AB (OFF_EI + (size_t)NEDGE)     // 69730304

#define EDGE_BLOCKS 1024                    // BT * 8
#define NODE_BLOCKS 128                     // BT

// Precomputed per-channel edge constants (all mean-centered over h so the
// LayerNorm mean folds away):
__device__ float g_wc[16 * 32];     // centered RBF weight rows 0..15
__device__ float g_base[32];        // centered (bias + vn-fold), |dir|=1 case
__device__ float g_dC[32];          // centered (self-case minus base-case)
__device__ float g_whv[32];         // wh @ wv  (v_out projection)
__device__ float g_epcc[575 * 32];  // centered  sum_k Epos_k(d) * W[16+k][h]

__device__ __forceinline__ float bfly_sum(float v) {
    #pragma unroll
    for (int o = 16; o; o >>= 1) v += __shfl_xor_sync(0xffffffffu, v, o);
    return v;
}

// ---------------------------------------------------------------------------
// Combined init, 73 blocks x 256:
//   blocks 0..71 : g_epcc rows (warp = one d value)
//   block  72    : per-channel folds + centered RBF rows
// ---------------------------------------------------------------------------
__global__ __launch_bounds__(256) void init_all_kernel(
    const float* __restrict__ e_wh, const float* __restrict__ e_wsw,
    const float* __restrict__ e_wsb, const float* __restrict__ e_wv)
{
    int w = threadIdx.x >> 5, l = threadIdx.x & 31;

    if (blockIdx.x < 72) {
        int g = blockIdx.x * 8 + w;
        if (g >= 575) return;
        // f_j = 10000^(-j/8), correctly rounded compile-time constants
        const float FR[8] = {
            1.0f, 0.31622776601683794f, 0.1f, 0.031622776601683791f,
            0.01f, 0.0031622776601683794f, 0.001f, 0.00031622776601683794f };
        float d = (float)(g - 63);
        float acc = 0.0f;
        #pragma unroll
        for (int j = 0; j < 8; j++) {
            float s, c;
            sincosf(d * FR[j], &s, &c);
            acc = fmaf(c, e_wsw[(16 + j) * 32 + l], acc);
            acc = fmaf(s, e_wsw[(24 + j) * 32 + l], acc);
        }
        g_epcc[g * 32 + l] = acc - bfly_sum(acc) * (1.0f / 32.0f);
    } else {
        __shared__ float sbase[32], sdC[32];
        // centered RBF rows (k, h = l): warps 0..7 cover k = w, w+8
        for (int k = w; k < 16; k += 8) {
            float wk = e_wsw[k * 32 + l];
            g_wc[k * 32 + l] = wk - bfly_sum(wk) * (1.0f / 32.0f);
        }
        // per-channel folds: h = w, w+8, w+16, w+24; lane = inner index m
        float whm = e_wh[l];
        float vnt = sqrtf(fmaf(whm, whm, 1e-8f));
        for (int h = w; h < 32; h += 8) {
            float wsv = e_wsw[(32 + l) * 32 + h];
            float wv  = e_wv[l * 32 + h];
            float vnc   = bfly_sum(vnt * wsv);
            float selfc = bfly_sum(sqrtf(1e-8f) * wsv);
            float whv   = bfly_sum(whm * wv);
            if (l == 0) {
                sbase[h] = e_wsb[h] + vnc;
                sdC[h]   = selfc - vnc;
                g_whv[h] = whv;
            }
        }
        __syncthreads();
        if (w == 0) {
            float b = sbase[l];
            g_base[l] = b - bfly_sum(b) * (1.0f / 32.0f);
            float dd = sdC[l];
            g_dC[l]   = dd - bfly_sum(dd) * (1.0f / 32.0f);
        }
    }
}

__device__ __forceinline__ void nrm3(float& x, float& y, float& z) {
    float n = sqrtf(x * x + y * y + z * z);
    float inv = 1.0f / fmaxf(n, 1e-12f);
    x *= inv; y *= inv; z *= inv;
}

// ---------------------------------------------------------------------------
// Mega kernel: blocks [0,1024) = fused sort+edge path, [1024,1152) = node path
// ---------------------------------------------------------------------------
__global__ __launch_bounds__(256) void mega_kernel(
    const float* __restrict__ X, const float* __restrict__ mask,
    const int* __restrict__ chain, const int* __restrict__ focus, int L,
    const float* __restrict__ n_wh,  const float* __restrict__ n_wsw,
    const float* __restrict__ n_wsb, const float* __restrict__ n_wv,
    const float* __restrict__ lnng,  const float* __restrict__ lnnb,
    const float* __restrict__ lneg,  const float* __restrict__ lneb,
    float* __restrict__ out)
{
    __shared__ __align__(16) char smraw[28416];
    int bx = blockIdx.x;
    int tid = threadIdx.x, w = tid >> 5, l = tid & 31;

    if (bx < EDGE_BLOCKS) {
        // ================= EDGE PATH (fused sort + features + GVP + LN) ====
        float* feat = (float*)smraw;              // 8*32*20 = 5120 (16B aligned)
        float* xca  = feat + 5120;                // 192
        float* msk  = xca + 192;                  // 64
        int*   foc  = (int*)(msk + 64);           // 64
        int*   chs  = foc + 64;                   // 512
        float* Drow = (float*)(chs + 512);        // 8*64
        int*   erow = (int*)(Drow + 512);         // 8*64

        int bt = bx >> 3, rg = bx & 7, b = bt >> 6;
        const float* Xbt = X + (size_t)bt * 768;
        for (int idx = tid; idx < 192; idx += 256)
            xca[idx] = Xbt[(idx / 3) * 12 + 3 + (idx % 3)];
        if (tid < 64) {
            msk[tid] = mask[bt * 64 + tid];
            foc[tid] = focus[bt * 64 + tid];
        }
        const int* chainB = chain + b * L;
        bool chsm = (L <= 512);
        if (chsm) for (int idx = tid; idx < L; idx += 256) chs[idx] = chainB[idx];
        __syncthreads();

        // per-lane centered weights / constants
        float wreg[16];
        #pragma unroll
        for (int k = 0; k < 16; k++) wreg[k] = g_wc[k * 32 + l];
        float baseC = g_base[l];
        float dCc   = g_dC[l];
        float whv   = g_whv[l];
        float lg = lneg[l], lb = lneb[l];

        // ---- per-warp row: distances + stable argsort (rank count) ----
        int i = rg * 8 + w;
        float xix = xca[i * 3], xiy = xca[i * 3 + 1], xiz = xca[i * 3 + 2];
        float mi = msk[i];

        int j0 = l, j1 = l + 32;
        float d0, d1, a0, a1;
        {
            float dx = __fadd_rn(xca[j0 * 3],     -xix);
            float dy = __fadd_rn(xca[j0 * 3 + 1], -xiy);
            float dz = __fadd_rn(xca[j0 * 3 + 2], -xiz);
            float s = __fadd_rn(__fadd_rn(__fmul_rn(dx, dx), __fmul_rn(dy, dy)), __fmul_rn(dz, dz));
            d0 = __fmul_rn(__fmul_rn(msk[j0], mi), sqrtf(__fadd_rn(s, 1e-6f)));
            dx = __fadd_rn(xca[j1 * 3],     -xix);
            dy = __fadd_rn(xca[j1 * 3 + 1], -xiy);
            dz = __fadd_rn(xca[j1 * 3 + 2], -xiz);
            s = __fadd_rn(__fadd_rn(__fmul_rn(dx, dx), __fmul_rn(dy, dy)), __fmul_rn(dz, dz));
            d1 = __fmul_rn(__fmul_rn(msk[j1], mi), sqrtf(__fadd_rn(s, 1e-6f)));
        }
        float mx = fmaxf(d0, d1);
        #pragma unroll
        for (int o = 16; o; o >>= 1) mx = fmaxf(mx, __shfl_xor_sync(0xffffffffu, mx, o));
        float dmax = mx + 1.0f;
        {
            float m20 = __fmul_rn(msk[j0], mi);
            float m21 = __fmul_rn(msk[j1], mi);
            a0 = __fadd_rn(d0, __fmul_rn(1.0f - m20, dmax));
            a1 = __fadd_rn(d1, __fmul_rn(1.0f - m21, dmax));
        }
        Drow[w * 64 + j0] = a0;
        Drow[w * 64 + j1] = a1;
        __syncwarp();
        int r0 = 0, r1 = 0;
        #pragma unroll 16
        for (int k = 0; k < 64; k++) {
            float dk = Drow[w * 64 + k];
            r0 += (int)(dk < a0) | ((int)(dk == a0) & (int)(k < j0));
            r1 += (int)(dk < a1) | ((int)(dk == a1) & (int)(k < j1));
        }
        erow[w * 64 + r0] = j0;
        erow[w * 64 + r1] = j1;
        __syncwarp();

        int nbr0 = erow[w * 64];
        int c0 = chsm ? chs[foc[nbr0]] : chainB[foc[nbr0]];
        size_t gebase = (size_t)bt * 4096 + (size_t)i * 64;
        float4* frl = (float4*)(feat + w * 640 + l * 20);
        const float* fw = feat + w * 640;

        for (int t2 = 0; t2 < 2; t2++) {
            // ---- phase 1: lane = edge, build 20-float feature row ----
            int e = t2 * 32 + l;
            int nbr = erow[w * 64 + e];
            float dn = Drow[w * 64 + nbr];
            int an = foc[nbr];
            size_t ge = gebase + e;
            out[OFF_EI + ge] = (float)nbr;
            out[OFF_AB + ge] = (float)an;

            float dx = xca[nbr * 3]     - xix;
            float dy = xca[nbr * 3 + 1] - xiy;
            float dz = xca[nbr * 3 + 2] - xiz;
            float n2 = dx * dx + dy * dy + dz * dz;
            float invn = 1.0f / fmaxf(sqrtf(n2), 1e-12f);

            // RBF (16 values, 4 float4s)
            #pragma unroll
            for (int q = 0; q < 4; q++) {
                float4 v;
                float t0 = (dn - (float)(4 * q + 0) * (20.0f / 15.0f)) * 0.8f;
                float t1 = (dn - (float)(4 * q + 1) * (20.0f / 15.0f)) * 0.8f;
                float tA = (dn - (float)(4 * q + 2) * (20.0f / 15.0f)) * 0.8f;
                float tB = (dn - (float)(4 * q + 3) * (20.0f / 15.0f)) * 0.8f;
                v.x = __expf(-t0 * t0); v.y = __expf(-t1 * t1);
                v.z = __expf(-tA * tA); v.w = __expf(-tB * tB);
                frl[q] = v;
            }
            {
                int same  = ((chsm ? chs[an] : chainB[an]) == c0) ? 1 : 0;
                int selff = (n2 == 0.0f) ? 1 : 0;
                int code = (an - i + 63) | (same << 10) | (selff << 11);
                float4 v = {dx * invn, dy * invn, dz * invn, (float)code};
                frl[4] = v;
            }
            __syncwarp();

            // ---- phase 2: lane = channel, 2-edge interleaved, LN-centered ----
            size_t eo_base = OFF_E + (gebase + (size_t)(t2 * 32)) * 128;
            for (int t = 0; t < 32; t += 2) {
                const float4* ra = (const float4*)(fw + t * 20);
                const float4* rb = (const float4*)(fw + t * 20 + 20);
                float4 ga = ra[4], gb = rb[4];
                int ca = (int)ga.w, cb = (int)gb.w;
                float ea = g_epcc[(ca & 1023) * 32 + l];
                float eb = g_epcc[(cb & 1023) * 32 + l];
                float sfa = (float)((ca >> 10) & 1), sfb = (float)((cb >> 10) & 1);
                float sla = (float)(ca >> 11),       slb = (float)(cb >> 11);
                // dv = s_out - mean  (all terms pre-centered over channels)
                float dv0 = fmaf(sla, dCc, baseC);
                float dv1 = fmaf(slb, dCc, baseC);
                dv0 = fmaf(sfa, ea, dv0);
                dv1 = fmaf(sfb, eb, dv1);
                #pragma unroll
                for (int q = 0; q < 4; q++) {
                    float4 av = ra[q], bv = rb[q];
                    dv0 = fmaf(av.x, wreg[4 * q + 0], dv0);
                    dv1 = fmaf(bv.x, wreg[4 * q + 0], dv1);
                    dv0 = fmaf(av.y, wreg[4 * q + 1], dv0);
                    dv1 = fmaf(bv.y, wreg[4 * q + 1], dv1);
                    dv0 = fmaf(av.z, wreg[4 * q + 2], dv0);
                    dv1 = fmaf(bv.z, wreg[4 * q + 2], dv1);
                    dv0 = fmaf(av.w, wreg[4 * q + 3], dv0);
                    dv1 = fmaf(bv.w, wreg[4 * q + 3], dv1);
                }
                // single variance butterfly per edge (2-way interleaved)
                float q0 = dv0 * dv0, q1 = dv1 * dv1;
                #pragma unroll
                for (int o = 16; o; o >>= 1) {
                    q0 += __shfl_xor_sync(0xffffffffu, q0, o);
                    q1 += __shfl_xor_sync(0xffffffffu, q1, o);
                }
                float iv0 = rsqrtf(fmaf(q0, 1.0f / 32.0f, 1e-5f));
                float iv1 = rsqrtf(fmaf(q1, 1.0f / 32.0f, 1e-5f));
                float so0 = fmaf(dv0 * iv0, lg, lb);
                float so1 = fmaf(dv1 * iv1, lg, lb);

                size_t eo = eo_base + (size_t)t * 128;
                out[eo + l]      = ga.x * whv;
                out[eo + 32 + l] = ga.y * whv;
                out[eo + 64 + l] = ga.z * whv;
                out[eo + 96 + l] = so0;
                eo += 128;
                out[eo + l]      = gb.x * whv;
                out[eo + 32 + l] = gb.y * whv;
                out[eo + 64 + l] = gb.z * whv;
                out[eo + 96 + l] = so1;
            }
            __syncwarp();
        }
    } else {
        // ========================= NODE PATH ===============================
        float* wsw  = (float*)smraw;          // 70*64
        float* whs  = wsw + 4480;             // 3*64
        float* whvs = whs + 192;              // 3*64
        float* wsb  = whvs + 192;             // 64
        float* glng = wsb + 64;               // 64
        float* glnb = glng + 64;              // 64
        float* sdi  = glnb + 64;              // 64*6
        float* vmat = sdi + 384;              // 64*9
        float* vnbuf = vmat + 576;            // 8*64 (16B aligned)

        int bt = bx - EDGE_BLOCKS;

        for (int idx = tid; idx < 4480; idx += 256) wsw[idx] = n_wsw[idx];
        for (int idx = tid; idx < 192; idx += 256)  whs[idx] = n_wh[idx];
        if (tid < 64) { wsb[tid] = n_wsb[tid]; glng[tid] = lnng[tid]; glnb[tid] = lnnb[tid]; }

        const float* Xbt = X + (size_t)bt * 768;
        if (tid < 192) {
            // dihedrals: one (i,t) per thread
            int i = tid / 3, t = tid - 3 * i;
            int r = 3 * i + t - 1;
            float ang = 0.0f;
            if (r >= 0 && r < 189) {
                float P[4][3];
                #pragma unroll
                for (int qq = 0; qq < 4; qq++) {
                    int p = r + qq;
                    const float* A = Xbt + (p / 3) * 12 + (p % 3) * 3;
                    P[qq][0] = A[0]; P[qq][1] = A[1]; P[qq][2] = A[2];
                }
                float u2x = P[1][0] - P[0][0], u2y = P[1][1] - P[0][1], u2z = P[1][2] - P[0][2];
                float u1x = P[2][0] - P[1][0], u1y = P[2][1] - P[1][1], u1z = P[2][2] - P[1][2];
                float u0x = P[3][0] - P[2][0], u0y = P[3][1] - P[2][1], u0z = P[3][2] - P[2][2];
                nrm3(u2x, u2y, u2z); nrm3(u1x, u1y, u1z); nrm3(u0x, u0y, u0z);
                float ax = u2y * u1z - u2z * u1y;
                float ay = u2z * u1x - u2x * u1z;
                float az = u2x * u1y - u2y * u1x; nrm3(ax, ay, az);
                float bx_ = u1y * u0z - u1z * u0y;
                float by_ = u1z * u0x - u1x * u0z;
                float bz_ = u1x * u0y - u1y * u0x; nrm3(bx_, by_, bz_);
                float cd = ax * bx_ + ay * by_ + az * bz_;
                cd = fminf(fmaxf(cd, -1.0f + 1e-7f), 1.0f - 1e-7f);
                float sg = u2x * bx_ + u2y * by_ + u2z * bz_;
                float sn = (sg > 0.f) ? 1.f : ((sg < 0.f) ? -1.f : 0.f);
                ang = sn * acosf(cd);
            }
            sdi[i * 6 + t]     = cosf(ang);
            sdi[i * 6 + 3 + t] = sinf(ang);
        } else {
            // frames: sidechain vec + fwd + bwd, one node per thread
            int i = tid - 192;
            const float* Xr = Xbt + (size_t)i * 12;
            float nx = Xr[0], ny = Xr[1], nz = Xr[2];
            float ox = Xr[3], oy = Xr[4], oz = Xr[5];
            float cx = Xr[6], cy = Xr[7], cz = Xr[8];
            float ccx = cx - ox, ccy = cy - oy, ccz = cz - oz; nrm3(ccx, ccy, ccz);
            float nnx = nx - ox, nny = ny - oy, nnz = nz - oz; nrm3(nnx, nny, nnz);
            float bxv = ccx + nnx, byv = ccy + nny, bzv = ccz + nnz; nrm3(bxv, byv, bzv);
            float px = ccy * nnz - ccz * nny;
            float py = ccz * nnx - ccx * nnz;
            float pz = ccx * nny - ccy * nnx; nrm3(px, py, pz);
            const float k1 = 0.57735026918962576f, k2 = 0.81649658092772603f;
            vmat[i * 9 + 0] = -bxv * k1 - px * k2;
            vmat[i * 9 + 3] = -byv * k1 - py * k2;
            vmat[i * 9 + 6] = -bzv * k1 - pz * k2;
            float fx = 0.f, fy = 0.f, fz = 0.f;
            if (i < 63) {
                const float* Xn2 = Xbt + (size_t)(i + 1) * 12 + 3;
                fx = Xn2[0] - ox; fy = Xn2[1] - oy; fz = Xn2[2] - oz; nrm3(fx, fy, fz);
            }
            vmat[i * 9 + 1] = fx; vmat[i * 9 + 4] = fy; vmat[i * 9 + 7] = fz;
            float gx = 0.f, gy = 0.f, gz = 0.f;
            if (i > 0) {
                const float* Xp = Xbt + (size_t)(i - 1) * 12 + 3;
                gx = ox - Xp[0]; gy = oy - Xp[1]; gz = oz - Xp[2]; nrm3(gx, gy, gz);
                gx = -gx; gy = -gy; gz = -gz;
            }
            vmat[i * 9 + 2] = gx; vmat[i * 9 + 5] = gy; vmat[i * 9 + 8] = gz;
        }
        __syncthreads();

        // whv = wh @ wv (3 x 64)
        for (int idx = tid; idx < 192; idx += 256) {
            int p = idx >> 6, h = idx & 63;
            float a = 0.f;
            for (int m = 0; m < 64; m++) a = fmaf(whs[p * 64 + m], n_wv[m * 64 + h], a);
            whvs[idx] = a;
        }
        __syncthreads();

        for (int nd = w; nd < 64; nd += 8) {
            float vm[9];
            #pragma unroll
            for (int z = 0; z < 9; z++) vm[z] = vmat[nd * 9 + z];
            int h0 = l, h1 = l + 32;
            float vh0[3], vh1[3];
            #pragma unroll
            for (int c = 0; c < 3; c++) {
                vh0[c] = vm[c * 3 + 0] * whs[0 * 64 + h0] + vm[c * 3 + 1] * whs[1 * 64 + h0] + vm[c * 3 + 2] * whs[2 * 64 + h0];
                vh1[c] = vm[c * 3 + 0] * whs[0 * 64 + h1] + vm[c * 3 + 1] * whs[1 * 64 + h1] + vm[c * 3 + 2] * whs[2 * 64 + h1];
            }
            float vn0 = sqrtf(vh0[0] * vh0[0] + vh0[1] * vh0[1] + vh0[2] * vh0[2] + 1e-8f);
            float vn1 = sqrtf(vh1[0] * vh1[0] + vh1[1] * vh1[1] + vh1[2] * vh1[2] + 1e-8f);
            vnbuf[w * 64 + l] = vn0;
            vnbuf[w * 64 + l + 32] = vn1;
            __syncwarp();

            float acc0 = wsb[h0], acc1 = wsb[h1];
            #pragma unroll
            for (int k = 0; k < 6; k++) {
                float dk = sdi[nd * 6 + k];
                acc0 = fmaf(dk, wsw[k * 64 + h0], acc0);
                acc1 = fmaf(dk, wsw[k * 64 + h1], acc1);
            }
            #pragma unroll
            for (int m = 0; m < 64; m += 4) {
                float4 v4 = *reinterpret_cast<const float4*>(&vnbuf[w * 64 + m]);
                acc0 = fmaf(v4.x, wsw[(6 + m) * 64 + h0], acc0);
                acc1 = fmaf(v4.x, wsw[(6 + m) * 64 + h1], acc1);
                acc0 = fmaf(v4.y, wsw[(7 + m) * 64 + h0], acc0);
                acc1 = fmaf(v4.y, wsw[(7 + m) * 64 + h1], acc1);
                acc0 = fmaf(v4.z, wsw[(8 + m) * 64 + h0], acc0);
                acc1 = fmaf(v4.z, wsw[(8 + m) * 64 + h1], acc1);
                acc0 = fmaf(v4.w, wsw[(9 + m) * 64 + h0], acc0);
                acc1 = fmaf(v4.w, wsw[(9 + m) * 64 + h1], acc1);
            }
            __syncwarp();

            // LayerNorm over 64 channels: 2 interleaved butterflies
            float ssum = acc0 + acc1;
            #pragma unroll
            for (int o = 16; o; o >>= 1) ssum += __shfl_xor_sync(0xffffffffu, ssum, o);
            float mean = ssum * (1.0f / 64.0f);
            float dv0 = acc0 - mean, dv1 = acc1 - mean;
            float vs = dv0 * dv0 + dv1 * dv1;
            #pragma unroll
            for (int o = 16; o; o >>= 1) vs += __shfl_xor_sync(0xffffffffu, vs, o);
            float inv = rsqrtf(vs * (1.0f / 64.0f) + 1e-5f);
            float o0 = dv0 * inv * glng[h0] + glnb[h0];
            float o1 = dv1 * inv * glng[h1] + glnb[h1];

            size_t vb = ((size_t)bt * 64 + nd) * 256;
            #pragma unroll
            for (int c = 0; c < 3; c++) {
                float vo0 = vm[c * 3 + 0] * whvs[0 * 64 + h0] + vm[c * 3 + 1] * whvs[1 * 64 + h0] + vm[c * 3 + 2] * whvs[2 * 64 + h0];
                float vo1 = vm[c * 3 + 0] * whvs[0 * 64 + h1] + vm[c * 3 + 1] * whvs[1 * 64 + h1] + vm[c * 3 + 2] * whvs[2 * 64 + h1];
                out[vb + c * 64 + h0] = vo0;
                out[vb + c * 64 + h1] = vo1;
            }
            out[vb + 192 + h0] = o0;
            out[vb + 192 + h1] = o1;
        }
    }
}

// ---------------------------------------------------------------------------
extern "C" void kernel_launch(void* const* d_in, const int* in_sizes, int n_in,
                              void* d_out, int out_size)
{
    const float* X      = (const float*)d_in[0];
    const float* mask   = (const float*)d_in[1];
    const int*   chain  = (const int*)d_in[2];
    const int*   focus  = (const int*)d_in[3];
    const float* n_wh   = (const float*)d_in[4];
    const float* n_wsw  = (const float*)d_in[5];
    const float* n_wsb  = (const float*)d_in[6];
    const float* n_wv   = (const float*)d_in[7];
    const float* e_wh   = (const float*)d_in[8];
    const float* e_wsw  = (const float*)d_in[9];
    const float* e_wsb  = (const float*)d_in[10];
    const float* e_wv   = (const float*)d_in[11];
    const float* ln_n_g = (const float*)d_in[12];
    const float* ln_n_b = (const float*)d_in[13];
    const float* ln_e_g = (const float*)d_in[14];
    const float* ln_e_b = (const float*)d_in[15];
    float* out = (float*)d_out;
    int L = in_sizes[2] / 2;

    init_all_kernel<<<73, 256>>>(e_wh, e_wsw, e_wsb, e_wv);
    mega_kernel<<<EDGE_BLOCKS + NODE_BLOCKS, 256>>>(
        X, mask, chain, focus, L,
        n_wh, n_wsw, n_wsb, n_wv,
        ln_n_g, ln_n_b, ln_e_g, ln_e_b, out);
}

// round 9
// speedup vs baseline: 3.4331x; 1.0625x over previous
#include <cuda_runtime.h>
#include <math.h>

// Problem constants
#define BT  128                             // B*T
#define NEDGE (BT * 64 * 64)                // 524288
#define V_SZ  ((size_t)BT * 64 * 256)       // 2097152
#define E_SZ  ((size_t)NEDGE * 128)         // 67108864
#define OFF_E  (V_SZ)
#define OFF_EI (OFF_E + E_SZ)               // 69206016
#define OFF_AB (OFF_EI + (size_t)NEDGE)     // 69730304

#define EDGE_BLOCKS 1024                    // BT * 8
#define NODE_BLOCKS 128                     // BT

// Precomputed per-channel edge constants (all mean-centered over h so the
// LayerNorm mean folds away):
__device__ float g_base[32];         // centered (bias + vn-fold), |dir|=1 case
__device__ float g_dC[32];           // centered (self-case minus base-case)
__device__ float g_whv[32];          // wh @ wv  (v_out projection)
__device__ float g_ctab[1024 * 32];  // rows [0,575): centered Epos@W; row 600: 0
__device__ float g_rbft[2048 * 32];  // centered RBF@W sampled at dn = r/64

__device__ __forceinline__ float bfly_sum(float v) {
    #pragma unroll
    for (int o = 16; o; o >>= 1) v += __shfl_xor_sync(0xffffffffu, v, o);
    return v;
}

// ---------------------------------------------------------------------------
// Combined init, 387 blocks x 256:
//   blocks [0,72)    : g_ctab rows 0..574 (centered Epos @ W)
//   blocks [72,130)  : zero g_ctab rows 575..1023
//   blocks [130,386) : g_rbft rows (centered RBF @ W at dn = r/64)
//   block  386       : per-channel folds (base / dC / whv)
// ---------------------------------------------------------------------------
__global__ __launch_bounds__(256) void init_all_kernel(
    const float* __restrict__ e_wh, const float* __restrict__ e_wsw,
    const float* __restrict__ e_wsb, const float* __restrict__ e_wv)
{
    int bxx = blockIdx.x;
    int w = threadIdx.x >> 5, l = threadIdx.x & 31;

    if (bxx < 72) {
        int g = bxx * 8 + w;
        if (g >= 575) return;
        const float FR[8] = {
            1.0f, 0.31622776601683794f, 0.1f, 0.031622776601683791f,
            0.01f, 0.0031622776601683794f, 0.001f, 0.00031622776601683794f };
        float d = (float)(g - 63);
        float acc = 0.0f;
        #pragma unroll
        for (int j = 0; j < 8; j++) {
            float s, c;
            sincosf(d * FR[j], &s, &c);
            acc = fmaf(c, e_wsw[(16 + j) * 32 + l], acc);
            acc = fmaf(s, e_wsw[(24 + j) * 32 + l], acc);
        }
        g_ctab[g * 32 + l] = acc - bfly_sum(acc) * (1.0f / 32.0f);
    } else if (bxx < 130) {
        int g = 575 + (bxx - 72) * 8 + w;
        if (g < 1024) g_ctab[g * 32 + l] = 0.0f;
    } else if (bxx < 386) {
        int r = (bxx - 130) * 8 + w;
        float dn = (float)r * (1.0f / 64.0f);
        float acc = 0.0f;
        #pragma unroll
        for (int k = 0; k < 16; k++) {
            float t = (dn - (float)k * (20.0f / 15.0f)) * 0.8f;
            acc = fmaf(expf(-t * t), e_wsw[k * 32 + l], acc);
        }
        g_rbft[r * 32 + l] = acc - bfly_sum(acc) * (1.0f / 32.0f);
    } else {
        __shared__ float sbase[32], sdC[32];
        // per-channel folds: h = w, w+8, w+16, w+24; lane = inner index m
        float whm = e_wh[l];
        float vnt = sqrtf(fmaf(whm, whm, 1e-8f));
        for (int h = w; h < 32; h += 8) {
            float wsv = e_wsw[(32 + l) * 32 + h];
            float wv  = e_wv[l * 32 + h];
            float vnc   = bfly_sum(vnt * wsv);
            float selfc = bfly_sum(sqrtf(1e-8f) * wsv);
            float whv   = bfly_sum(whm * wv);
            if (l == 0) {
                sbase[h] = e_wsb[h] + vnc;
                sdC[h]   = selfc - vnc;
                g_whv[h] = whv;
            }
        }
        __syncthreads();
        if (w == 0) {
            float b = sbase[l];
            g_base[l] = b - bfly_sum(b) * (1.0f / 32.0f);
            float dd = sdC[l];
            g_dC[l]   = dd - bfly_sum(dd) * (1.0f / 32.0f);
        }
    }
}

__device__ __forceinline__ void nrm3(float& x, float& y, float& z) {
    float n = sqrtf(x * x + y * y + z * z);
    float inv = 1.0f / fmaxf(n, 1e-12f);
    x *= inv; y *= inv; z *= inv;
}

// ---------------------------------------------------------------------------
// Mega kernel: blocks [0,1024) = fused sort+edge path, [1024,1152) = node path
// ---------------------------------------------------------------------------
__global__ __launch_bounds__(256) void mega_kernel(
    const float* __restrict__ X, const float* __restrict__ mask,
    const int* __restrict__ chain, const int* __restrict__ focus, int L,
    const float* __restrict__ n_wh,  const float* __restrict__ n_wsw,
    const float* __restrict__ n_wsb, const float* __restrict__ n_wv,
    const float* __restrict__ lnng,  const float* __restrict__ lnnb,
    const float* __restrict__ lneg,  const float* __restrict__ lneb,
    float* __restrict__ out)
{
    __shared__ __align__(16) char smraw[26624];
    int bx = blockIdx.x;
    int tid = threadIdx.x, w = tid >> 5, l = tid & 31;

    if (bx < EDGE_BLOCKS) {
        // ================= EDGE PATH (fused sort + features + GVP + LN) ====
        float* feat = (float*)smraw;              // 8*32*8 = 2048 (16B aligned)
        float* xca  = feat + 2048;                // 192
        float* msk  = xca + 192;                  // 64
        int*   foc  = (int*)(msk + 64);           // 64
        int*   chs  = foc + 64;                   // 512
        float* Drow = (float*)(chs + 512);        // 8*64
        int*   erow = (int*)(Drow + 512);         // 8*64

        int bt = bx >> 3, rg = bx & 7, b = bt >> 6;
        const float* Xbt = X + (size_t)bt * 768;
        for (int idx = tid; idx < 192; idx += 256)
            xca[idx] = Xbt[(idx / 3) * 12 + 3 + (idx % 3)];
        if (tid < 64) {
            msk[tid] = mask[bt * 64 + tid];
            foc[tid] = focus[bt * 64 + tid];
        }
        const int* chainB = chain + b * L;
        bool chsm = (L <= 512);
        if (chsm) for (int idx = tid; idx < L; idx += 256) chs[idx] = chainB[idx];
        __syncthreads();

        // per-lane constants
        float baseC = g_base[l];
        float dCc   = g_dC[l];
        float whv   = g_whv[l];
        float lg = lneg[l], lb = lneb[l];

        // ---- per-warp row: distances + stable argsort (rank count) ----
        int i = rg * 8 + w;
        float xix = xca[i * 3], xiy = xca[i * 3 + 1], xiz = xca[i * 3 + 2];
        float mi = msk[i];

        int j0 = l, j1 = l + 32;
        float d0, d1, a0_, a1_;
        {
            float dx = __fadd_rn(xca[j0 * 3],     -xix);
            float dy = __fadd_rn(xca[j0 * 3 + 1], -xiy);
            float dz = __fadd_rn(xca[j0 * 3 + 2], -xiz);
            float s = __fadd_rn(__fadd_rn(__fmul_rn(dx, dx), __fmul_rn(dy, dy)), __fmul_rn(dz, dz));
            d0 = __fmul_rn(__fmul_rn(msk[j0], mi), sqrtf(__fadd_rn(s, 1e-6f)));
            dx = __fadd_rn(xca[j1 * 3],     -xix);
            dy = __fadd_rn(xca[j1 * 3 + 1], -xiy);
            dz = __fadd_rn(xca[j1 * 3 + 2], -xiz);
            s = __fadd_rn(__fadd_rn(__fmul_rn(dx, dx), __fmul_rn(dy, dy)), __fmul_rn(dz, dz));
            d1 = __fmul_rn(__fmul_rn(msk[j1], mi), sqrtf(__fadd_rn(s, 1e-6f)));
        }
        float mx = fmaxf(d0, d1);
        #pragma unroll
        for (int o = 16; o; o >>= 1) mx = fmaxf(mx, __shfl_xor_sync(0xffffffffu, mx, o));
        float dmax = mx + 1.0f;
        {
            float m20 = __fmul_rn(msk[j0], mi);
            float m21 = __fmul_rn(msk[j1], mi);
            a0_ = __fadd_rn(d0, __fmul_rn(1.0f - m20, dmax));
            a1_ = __fadd_rn(d1, __fmul_rn(1.0f - m21, dmax));
        }
        Drow[w * 64 + j0] = a0_;
        Drow[w * 64 + j1] = a1_;
        __syncwarp();
        int r0 = 0, r1 = 0;
        #pragma unroll 16
        for (int k = 0; k < 64; k++) {
            float dk = Drow[w * 64 + k];
            r0 += (int)(dk < a0_) | ((int)(dk == a0_) & (int)(k < j0));
            r1 += (int)(dk < a1_) | ((int)(dk == a1_) & (int)(k < j1));
        }
        erow[w * 64 + r0] = j0;
        erow[w * 64 + r1] = j1;
        __syncwarp();

        int nbr0 = erow[w * 64];
        int c0 = chsm ? chs[foc[nbr0]] : chainB[foc[nbr0]];
        size_t gebase = (size_t)bt * 4096 + (size_t)i * 64;
        float* frl = feat + w * 256 + l * 8;
        const float* fw = feat + w * 256;

        for (int t2 = 0; t2 < 2; t2++) {
            // ---- phase 1: lane = edge, build 8-float feature row ----
            int e = t2 * 32 + l;
            int nbr = erow[w * 64 + e];
            float dn = Drow[w * 64 + nbr];
            int an = foc[nbr];
            size_t ge = gebase + e;
            out[OFF_EI + ge] = (float)nbr;
            out[OFF_AB + ge] = (float)an;

            float dx = xca[nbr * 3]     - xix;
            float dy = xca[nbr * 3 + 1] - xiy;
            float dz = xca[nbr * 3 + 2] - xiz;
            float n2 = dx * dx + dy * dy + dz * dz;
            float invn = 1.0f / fmaxf(sqrtf(n2), 1e-12f);

            int same  = ((chsm ? chs[an] : chainB[an]) == c0);
            int selff = (n2 == 0.0f) ? 1 : 0;
            int code = (same ? (an - i + 63) : 600) | (selff << 10);
            float dn64 = fminf(dn * 64.0f, 2045.0f);
            {
                float4 v = {dx * invn, dy * invn, dz * invn, __int_as_float(code)};
                *reinterpret_cast<float4*>(frl) = v;
                frl[4] = dn64;
            }
            __syncwarp();

            // ---- phase 2: lane = channel, 2-edge interleaved, LN-centered ----
            float* po = out + (OFF_E + (gebase + (size_t)(t2 * 32)) * 128) + l;
            for (int t = 0; t < 32; t += 2) {
                const float* pa = fw + t * 8;
                float4 ga = *reinterpret_cast<const float4*>(pa);
                float dna = pa[4];
                float4 gb = *reinterpret_cast<const float4*>(pa + 8);
                float dnb = pa[12];
                int ca = __float_as_int(ga.w), cb = __float_as_int(gb.w);
                float cta = g_ctab[(ca & 1023) * 32 + l];
                float ctb = g_ctab[(cb & 1023) * 32 + l];
                int ia = (int)dna, ib = (int)dnb;
                float fa = dna - (float)ia, fb = dnb - (float)ib;
                const float* rta = g_rbft + ia * 32 + l;
                const float* rtb = g_rbft + ib * 32 + l;
                float ra0 = rta[0], ra1 = rta[32];
                float rb0 = rtb[0], rb1 = rtb[32];
                float dv0 = fmaf(fa, ra1 - ra0, ra0 + cta);
                float dv1 = fmaf(fb, rb1 - rb0, rb0 + ctb);
                dv0 += fmaf((float)(ca >> 10), dCc, baseC);
                dv1 += fmaf((float)(cb >> 10), dCc, baseC);

                // single variance butterfly per edge (2-way interleaved)
                float q0 = dv0 * dv0, q1 = dv1 * dv1;
                #pragma unroll
                for (int o = 16; o; o >>= 1) {
                    q0 += __shfl_xor_sync(0xffffffffu, q0, o);
                    q1 += __shfl_xor_sync(0xffffffffu, q1, o);
                }
                float iv0 = rsqrtf(fmaf(q0, 1.0f / 32.0f, 1e-5f));
                float iv1 = rsqrtf(fmaf(q1, 1.0f / 32.0f, 1e-5f));
                float so0 = fmaf(dv0 * iv0, lg, lb);
                float so1 = fmaf(dv1 * iv1, lg, lb);

                po[0]   = ga.x * whv;
                po[32]  = ga.y * whv;
                po[64]  = ga.z * whv;
                po[96]  = so0;
                po[128] = gb.x * whv;
                po[160] = gb.y * whv;
                po[192] = gb.z * whv;
                po[224] = so1;
                po += 256;
            }
            __syncwarp();
        }
    } else {
        // ========================= NODE PATH ===============================
        float* wsw  = (float*)smraw;          // 70*64
        float* whs  = wsw + 4480;             // 3*64
        float* whvs = whs + 192;              // 3*64
        float* wsb  = whvs + 192;             // 64
        float* glng = wsb + 64;               // 64
        float* glnb = glng + 64;              // 64
        float* sdi  = glnb + 64;              // 64*6
        float* vmat = sdi + 384;              // 64*9
        float* vnbuf = vmat + 576;            // 8*64 (16B aligned)

        int bt = bx - EDGE_BLOCKS;

        for (int idx = tid; idx < 4480; idx += 256) wsw[idx] = n_wsw[idx];
        for (int idx = tid; idx < 192; idx += 256)  whs[idx] = n_wh[idx];
        if (tid < 64) { wsb[tid] = n_wsb[tid]; glng[tid] = lnng[tid]; glnb[tid] = lnnb[tid]; }

        const float* Xbt = X + (size_t)bt * 768;
        if (tid < 192) {
            // dihedrals: one (i,t) per thread
            int i = tid / 3, t = tid - 3 * i;
            int r = 3 * i + t - 1;
            float ang = 0.0f;
            if (r >= 0 && r < 189) {
                float P[4][3];
                #pragma unroll
                for (int qq = 0; qq < 4; qq++) {
                    int p = r + qq;
                    const float* A = Xbt + (p / 3) * 12 + (p % 3) * 3;
                    P[qq][0] = A[0]; P[qq][1] = A[1]; P[qq][2] = A[2];
                }
                float u2x = P[1][0] - P[0][0], u2y = P[1][1] - P[0][1], u2z = P[1][2] - P[0][2];
                float u1x = P[2][0] - P[1][0], u1y = P[2][1] - P[1][1], u1z = P[2][2] - P[1][2];
                float u0x = P[3][0] - P[2][0], u0y = P[3][1] - P[2][1], u0z = P[3][2] - P[2][2];
                nrm3(u2x, u2y, u2z); nrm3(u1x, u1y, u1z); nrm3(u0x, u0y, u0z);
                float ax = u2y * u1z - u2z * u1y;
                float ay = u2z * u1x - u2x * u1z;
                float az = u2x * u1y - u2y * u1x; nrm3(ax, ay, az);
                float bx_ = u1y * u0z - u1z * u0y;
                float by_ = u1z * u0x - u1x * u0z;
                float bz_ = u1x * u0y - u1y * u0x; nrm3(bx_, by_, bz_);
                float cd = ax * bx_ + ay * by_ + az * bz_;
                cd = fminf(fmaxf(cd, -1.0f + 1e-7f), 1.0f - 1e-7f);
                float sg = u2x * bx_ + u2y * by_ + u2z * bz_;
                float sn = (sg > 0.f) ? 1.f : ((sg < 0.f) ? -1.f : 0.f);
                ang = sn * acosf(cd);
            }
            sdi[i * 6 + t]     = cosf(ang);
            sdi[i * 6 + 3 + t] = sinf(ang);
        } else {
            // frames: sidechain vec + fwd + bwd, one node per thread
            int i = tid - 192;
            const float* Xr = Xbt + (size_t)i * 12;
            float nx = Xr[0], ny = Xr[1], nz = Xr[2];
            float ox = Xr[3], oy = Xr[4], oz = Xr[5];
            float cx = Xr[6], cy = Xr[7], cz = Xr[8];
            float ccx = cx - ox, ccy = cy - oy, ccz = cz - oz; nrm3(ccx, ccy, ccz);
            float nnx = nx - ox, nny = ny - oy, nnz = nz - oz; nrm3(nnx, nny, nnz);
            float bxv = ccx + nnx, byv = ccy + nny, bzv = ccz + nnz; nrm3(bxv, byv, bzv);
            float px = ccy * nnz - ccz * nny;
            float py = ccz * nnx - ccx * nnz;
            float pz = ccx * nny - ccy * nnx; nrm3(px, py, pz);
            const float k1 = 0.57735026918962576f, k2 = 0.81649658092772603f;
            vmat[i * 9 + 0] = -bxv * k1 - px * k2;
            vmat[i * 9 + 3] = -byv * k1 - py * k2;
            vmat[i * 9 + 6] = -bzv * k1 - pz * k2;
            float fx = 0.f, fy = 0.f, fz = 0.f;
            if (i < 63) {
                const float* Xn2 = Xbt + (size_t)(i + 1) * 12 + 3;
                fx = Xn2[0] - ox; fy = Xn2[1] - oy; fz = Xn2[2] - oz; nrm3(fx, fy, fz);
            }
            vmat[i * 9 + 1] = fx; vmat[i * 9 + 4] = fy; vmat[i * 9 + 7] = fz;
            float gx = 0.f, gy = 0.f, gz = 0.f;
            if (i > 0) {
                const float* Xp = Xbt + (size_t)(i - 1) * 12 + 3;
                gx = ox - Xp[0]; gy = oy - Xp[1]; gz = oz - Xp[2]; nrm3(gx, gy, gz);
                gx = -gx; gy = -gy; gz = -gz;
            }
            vmat[i * 9 + 2] = gx; vmat[i * 9 + 5] = gy; vmat[i * 9 + 8] = gz;
        }
        __syncthreads();

        // whv = wh @ wv (3 x 64)
        for (int idx = tid; idx < 192; idx += 256) {
            int p = idx >> 6, h = idx & 63;
            float a = 0.f;
            for (int m = 0; m < 64; m++) a = fmaf(whs[p * 64 + m], n_wv[m * 64 + h], a);
            whvs[idx] = a;
        }
        __syncthreads();

        for (int nd = w; nd < 64; nd += 8) {
            float vm[9];
            #pragma unroll
            for (int z = 0; z < 9; z++) vm[z] = vmat[nd * 9 + z];
            int h0 = l, h1 = l + 32;
            float vh0[3], vh1[3];
            #pragma unroll
            for (int c = 0; c < 3; c++) {
                vh0[c] = vm[c * 3 + 0] * whs[0 * 64 + h0] + vm[c * 3 + 1] * whs[1 * 64 + h0] + vm[c * 3 + 2] * whs[2 * 64 + h0];
                vh1[c] = vm[c * 3 + 0] * whs[0 * 64 + h1] + vm[c * 3 + 1] * whs[1 * 64 + h1] + vm[c * 3 + 2] * whs[2 * 64 + h1];
            }
            float vn0 = sqrtf(vh0[0] * vh0[0] + vh0[1] * vh0[1] + vh0[2] * vh0[2] + 1e-8f);
            float vn1 = sqrtf(vh1[0] * vh1[0] + vh1[1] * vh1[1] + vh1[2] * vh1[2] + 1e-8f);
            vnbuf[w * 64 + l] = vn0;
            vnbuf[w * 64 + l + 32] = vn1;
            __syncwarp();

            float acc0 = wsb[h0], acc1 = wsb[h1];
            #pragma unroll
            for (int k = 0; k < 6; k++) {
                float dk = sdi[nd * 6 + k];
                acc0 = fmaf(dk, wsw[k * 64 + h0], acc0);
                acc1 = fmaf(dk, wsw[k * 64 + h1], acc1);
            }
            #pragma unroll
            for (int m = 0; m < 64; m += 4) {
                float4 v4 = *reinterpret_cast<const float4*>(&vnbuf[w * 64 + m]);
                acc0 = fmaf(v4.x, wsw[(6 + m) * 64 + h0], acc0);
                acc1 = fmaf(v4.x, wsw[(6 + m) * 64 + h1], acc1);
                acc0 = fmaf(v4.y, wsw[(7 + m) * 64 + h0], acc0);
                acc1 = fmaf(v4.y, wsw[(7 + m) * 64 + h1], acc1);
                acc0 = fmaf(v4.z, wsw[(8 + m) * 64 + h0], acc0);
                acc1 = fmaf(v4.z, wsw[(8 + m) * 64 + h1], acc1);
                acc0 = fmaf(v4.w, wsw[(9 + m) * 64 + h0], acc0);
                acc1 = fmaf(v4.w, wsw[(9 + m) * 64 + h1], acc1);
            }
            __syncwarp();

            // LayerNorm over 64 channels: 2 interleaved butterflies
            float ssum = acc0 + acc1;
            #pragma unroll
            for (int o = 16; o; o >>= 1) ssum += __shfl_xor_sync(0xffffffffu, ssum, o);
            float mean = ssum * (1.0f / 64.0f);
            float dv0 = acc0 - mean, dv1 = acc1 - mean;
            float vs = dv0 * dv0 + dv1 * dv1;
            #pragma unroll
            for (int o = 16; o; o >>= 1) vs += __shfl_xor_sync(0xffffffffu, vs, o);
            float inv = rsqrtf(vs * (1.0f / 64.0f) + 1e-5f);
            float o0 = dv0 * inv * glng[h0] + glnb[h0];
            float o1 = dv1 * inv * glng[h1] + glnb[h1];

            size_t vb = ((size_t)bt * 64 + nd) * 256;
            #pragma unroll
            for (int c = 0; c < 3; c++) {
                float vo0 = vm[c * 3 + 0] * whvs[0 * 64 + h0] + vm[c * 3 + 1] * whvs[1 * 64 + h0] + vm[c * 3 + 2] * whvs[2 * 64 + h0];
                float vo1 = vm[c * 3 + 0] * whvs[0 * 64 + h1] + vm[c * 3 + 1] * whvs[1 * 64 + h1] + vm[c * 3 + 2] * whvs[2 * 64 + h1];
                out[vb + c * 64 + h0] = vo0;
                out[vb + c * 64 + h1] = vo1;
            }
            out[vb + 192 + h0] = o0;
            out[vb + 192 + h1] = o1;
        }
    }
}

// ---------------------------------------------------------------------------
extern "C" void kernel_launch(void* const* d_in, const int* in_sizes, int n_in,
                              void* d_out, int out_size)
{
    const float* X      = (const float*)d_in[0];
    const float* mask   = (const float*)d_in[1];
    const int*   chain  = (const int*)d_in[2];
    const int*   focus  = (const int*)d_in[3];
    const float* n_wh   = (const float*)d_in[4];
    const float* n_wsw  = (const float*)d_in[5];
    const float* n_wsb  = (const float*)d_in[6];
    const float* n_wv   = (const float*)d_in[7];
    const float* e_wh   = (const float*)d_in[8];
    const float* e_wsw  = (const float*)d_in[9];
    const float* e_wsb  = (const float*)d_in[10];
    const float* e_wv   = (const float*)d_in[11];
    const float* ln_n_g = (const float*)d_in[12];
    const float* ln_n_b = (const float*)d_in[13];
    const float* ln_e_g = (const float*)d_in[14];
    const float* ln_e_b = (const float*)d_in[15];
    float* out = (float*)d_out;
    int L = in_sizes[2] / 2;

    init_all_kernel<<<387, 256>>>(e_wh, e_wsw, e_wsb, e_wv);
    mega_kernel<<<EDGE_BLOCKS + NODE_BLOCKS, 256>>>(
        X, mask, chain, focus, L,
        n_wh, n_wsw, n_wsb, n_wv,
        ln_n_g, ln_n_b, ln_e_g, ln_e_b, out);
}